// round 1
// baseline (speedup 1.0000x reference)
#include <cuda_runtime.h>
#include <cuda_bf16.h>

#define BB 8
#define CC 128
#define TT 128
#define FF 512
#define KK 64
#define S_SIDE (TT*FF)   /* 65536 */
#define S_LAT  (TT*KK)   /* 8192  */

// ---------------- scratch (static device globals; no allocation) ----------------
__device__ float g_buf1[BB*CC*S_SIDE];   // norm(side) / att
__device__ float g_buf2[BB*CC*S_SIDE];   // glu out / q / glu2 out
__device__ float g_buf3[BB*CC*S_SIDE];   // query_h
__device__ float g_lh [BB*CC*S_LAT];
__device__ float g_k  [BB*CC*S_LAT];
__device__ float g_v  [BB*CC*S_LAT];

__device__ __forceinline__ float silu_f(float x) {
    return x / (1.0f + __expf(-x));
}

// ---------------- RMSNorm over channel dim ----------------
// X,Y: [B, C, S]; each thread handles 4 consecutive spatial positions.
__global__ __launch_bounds__(256)
void rmsnorm_kernel(const float* __restrict__ X, const float* __restrict__ gamma,
                    float* __restrict__ Y, int S)
{
    int b = blockIdx.y;
    int s = blockIdx.x * 1024 + threadIdx.x * 4;
    const float* xb = X + (size_t)b * CC * S + s;
    float* yb = Y + (size_t)b * CC * S + s;

    float4 acc = make_float4(0.f, 0.f, 0.f, 0.f);
    #pragma unroll 4
    for (int c = 0; c < CC; c++) {
        float4 v = *(const float4*)(xb + (size_t)c * S);
        acc.x += v.x * v.x; acc.y += v.y * v.y;
        acc.z += v.z * v.z; acc.w += v.w * v.w;
    }
    const float inv = 1.0f / CC;
    float4 r;
    r.x = rsqrtf(acc.x * inv + 1e-6f);
    r.y = rsqrtf(acc.y * inv + 1e-6f);
    r.z = rsqrtf(acc.z * inv + 1e-6f);
    r.w = rsqrtf(acc.w * inv + 1e-6f);
    #pragma unroll 4
    for (int c = 0; c < CC; c++) {
        float g = gamma[c];
        float4 v = *(const float4*)(xb + (size_t)c * S);
        v.x *= r.x * g; v.y *= r.y * g; v.z *= r.z * g; v.w *= r.w * g;
        *(float4*)(yb + (size_t)c * S) = v;
    }
}

// ---------------- GEMM: Y[b][o,s] = epi(sum_c W[o,c] * X[b][c,s] + bias[o]) ----------------
// ACT: 0 none, 1 silu.  EPI: 0 none, 1 += (*sc_p)*extra, 2 += Y(existing)
template<int ACT, int EPI>
__global__ __launch_bounds__(256)
void gemm128_kernel(const float* __restrict__ X, const float* __restrict__ W,
                    const float* __restrict__ bias, float* __restrict__ Y,
                    const float* __restrict__ extra, const float* __restrict__ sc_p, int S)
{
    __shared__ float Ws[16][136];
    __shared__ float Xs[16][128];
    int b  = blockIdx.y;
    int s0 = blockIdx.x * 128;
    int tid = threadIdx.x;
    int tx = tid & 15, ty = tid >> 4;   // tx: s-group of 8, ty: o-group of 8
    const float* Xb = X + (size_t)b * CC * S;

    float acc[8][8];
    #pragma unroll
    for (int i = 0; i < 8; i++)
        #pragma unroll
        for (int j = 0; j < 8; j++) acc[i][j] = 0.f;

    for (int kk = 0; kk < CC; kk += 16) {
        #pragma unroll
        for (int it = 0; it < 2; it++) {
            int t = tid + it * 256;          // 0..511
            int o = t >> 2, cq = t & 3;
            float4 w4 = *(const float4*)(W + o * CC + kk + cq * 4);
            Ws[cq*4+0][o] = w4.x; Ws[cq*4+1][o] = w4.y;
            Ws[cq*4+2][o] = w4.z; Ws[cq*4+3][o] = w4.w;
        }
        #pragma unroll
        for (int it = 0; it < 2; it++) {
            int t = tid + it * 256;
            int k = t >> 5, sq = t & 31;
            float4 x4 = *(const float4*)(Xb + (size_t)(kk + k) * S + s0 + sq * 4);
            *(float4*)&Xs[k][sq * 4] = x4;
        }
        __syncthreads();
        #pragma unroll
        for (int k = 0; k < 16; k++) {
            float4 w0 = *(const float4*)&Ws[k][ty * 8];
            float4 w1 = *(const float4*)&Ws[k][ty * 8 + 4];
            float4 x0 = *(const float4*)&Xs[k][tx * 8];
            float4 x1 = *(const float4*)&Xs[k][tx * 8 + 4];
            float wv[8] = {w0.x,w0.y,w0.z,w0.w,w1.x,w1.y,w1.z,w1.w};
            float xv[8] = {x0.x,x0.y,x0.z,x0.w,x1.x,x1.y,x1.z,x1.w};
            #pragma unroll
            for (int i = 0; i < 8; i++)
                #pragma unroll
                for (int j = 0; j < 8; j++)
                    acc[i][j] += wv[i] * xv[j];
        }
        __syncthreads();
    }

    float scl = (EPI == 1) ? *sc_p : 0.f;
    #pragma unroll
    for (int i = 0; i < 8; i++) {
        int o = ty * 8 + i;
        float bv = bias[o];
        float* yrow = Y + ((size_t)b * CC + o) * S + s0 + tx * 8;
        const float* erow = (EPI == 1) ? (extra + ((size_t)b * CC + o) * S + s0 + tx * 8) : nullptr;
        float out[8];
        #pragma unroll
        for (int j = 0; j < 8; j++) {
            float v = acc[i][j] + bv;
            if (ACT == 1) v = silu_f(v);
            if (EPI == 1) v += scl * erow[j];
            if (EPI == 2) v += yrow[j];
            out[j] = v;
        }
        *(float4*)(yrow + 0) = make_float4(out[0], out[1], out[2], out[3]);
        *(float4*)(yrow + 4) = make_float4(out[4], out[5], out[6], out[7]);
    }
}

// ---------------- Dual GEMM GLU: U = (Wa X + ba) * silu(Wg X + bg) ----------------
// W: [2C, C]; Wa = rows 0..C-1, Wg = rows C..2C-1. Tile: 128 o x 64 s.
__global__ __launch_bounds__(256)
void gemm_glu_kernel(const float* __restrict__ X, const float* __restrict__ W,
                     const float* __restrict__ bias, float* __restrict__ Y, int S)
{
    __shared__ float Wa[16][136];
    __shared__ float Wg[16][136];
    __shared__ float Xs[16][64];
    int b  = blockIdx.y;
    int s0 = blockIdx.x * 64;
    int tid = threadIdx.x;
    int tx = tid & 7, ty = tid >> 3;    // tx: s-group of 8 (64 s), ty: o-group of 4 (128 o)
    const float* Xb = X + (size_t)b * CC * S;

    float a1[4][8], a2[4][8];
    #pragma unroll
    for (int i = 0; i < 4; i++)
        #pragma unroll
        for (int j = 0; j < 8; j++) { a1[i][j] = 0.f; a2[i][j] = 0.f; }

    for (int kk = 0; kk < CC; kk += 16) {
        #pragma unroll
        for (int it = 0; it < 2; it++) {
            int t = tid + it * 256;
            int o = t >> 2, cq = t & 3;
            float4 w4 = *(const float4*)(W + o * CC + kk + cq * 4);
            Wa[cq*4+0][o] = w4.x; Wa[cq*4+1][o] = w4.y;
            Wa[cq*4+2][o] = w4.z; Wa[cq*4+3][o] = w4.w;
            float4 g4 = *(const float4*)(W + (o + CC) * CC + kk + cq * 4);
            Wg[cq*4+0][o] = g4.x; Wg[cq*4+1][o] = g4.y;
            Wg[cq*4+2][o] = g4.z; Wg[cq*4+3][o] = g4.w;
        }
        {
            int k = tid >> 4, sq = tid & 15;
            float4 x4 = *(const float4*)(Xb + (size_t)(kk + k) * S + s0 + sq * 4);
            *(float4*)&Xs[k][sq * 4] = x4;
        }
        __syncthreads();
        #pragma unroll
        for (int k = 0; k < 16; k++) {
            float4 x0 = *(const float4*)&Xs[k][tx * 8];
            float4 x1 = *(const float4*)&Xs[k][tx * 8 + 4];
            float4 wv = *(const float4*)&Wa[k][ty * 4];
            float4 gv = *(const float4*)&Wg[k][ty * 4];
            float xv[8] = {x0.x,x0.y,x0.z,x0.w,x1.x,x1.y,x1.z,x1.w};
            float wa4[4] = {wv.x,wv.y,wv.z,wv.w};
            float wg4[4] = {gv.x,gv.y,gv.z,gv.w};
            #pragma unroll
            for (int i = 0; i < 4; i++)
                #pragma unroll
                for (int j = 0; j < 8; j++) {
                    a1[i][j] += wa4[i] * xv[j];
                    a2[i][j] += wg4[i] * xv[j];
                }
        }
        __syncthreads();
    }

    #pragma unroll
    for (int i = 0; i < 4; i++) {
        int o = ty * 4 + i;
        float ba = bias[o], bg = bias[CC + o];
        float* yrow = Y + ((size_t)b * CC + o) * S + s0 + tx * 8;
        float out[8];
        #pragma unroll
        for (int j = 0; j < 8; j++) {
            float a = a1[i][j] + ba;
            float g = a2[i][j] + bg;
            out[j] = a * silu_f(g);
        }
        *(float4*)(yrow + 0) = make_float4(out[0], out[1], out[2], out[3]);
        *(float4*)(yrow + 4) = make_float4(out[4], out[5], out[6], out[7]);
    }
}

// ---------------- Attention: per (b, t, 128-wide f chunk) ----------------
// scores[f,k] = ss * sum_c q[c,f] k[c,k] + ps * basis[k, f]; softmax over k;
// att[c,f] = sum_k w[f,k] v[c,k]
#define ATT_SMEM_FLOATS (128*72 + 2*64*136)
#define ATT_SMEM_BYTES  (ATT_SMEM_FLOATS * 4)

__global__ __launch_bounds__(256)
void attn_kernel(const float* __restrict__ q, const float* __restrict__ kmat,
                 const float* __restrict__ vmat, const float* __restrict__ basis,
                 const float* __restrict__ ss_p, const float* __restrict__ ps_p,
                 float* __restrict__ att)
{
    extern __shared__ float sm[];
    float* Ks  = sm;                 // [128][72]   (c-major, padded)
    float* Qs  = sm + 128 * 72;      // [128][128]  (overlaid below after phase 1)
    float* Vt  = Qs;                 // [64][136]   k-major v
    float* Wsm = Qs + 64 * 136;      // [64][136]   k-major weights

    int fb = blockIdx.x * 128;
    int t  = blockIdx.y;
    int b  = blockIdx.z;
    int tid = threadIdx.x;
    int tx = tid & 15, ty = tid >> 4;

    const float* kb = kmat + (size_t)b * CC * S_LAT + t * KK;
    #pragma unroll
    for (int it = 0; it < 8; it++) {
        int idx = tid + it * 256;          // 0..2047
        int c = idx >> 4, kq = idx & 15;
        float4 v = *(const float4*)(kb + (size_t)c * S_LAT + kq * 4);
        *(float4*)&Ks[c * 72 + kq * 4] = v;
    }
    const float* qb = q + (size_t)b * CC * S_SIDE + t * FF + fb;
    #pragma unroll
    for (int it = 0; it < 16; it++) {
        int idx = tid + it * 256;          // 0..4095
        int c = idx >> 5, fq = idx & 31;
        float4 v = *(const float4*)(qb + (size_t)c * S_SIDE + fq * 4);
        *(float4*)&Qs[c * 128 + fq * 4] = v;
    }
    __syncthreads();

    // phase 1: scores tile [128 f][64 k], micro 8f x 4k per thread
    float sc[8][4];
    #pragma unroll
    for (int i = 0; i < 8; i++)
        #pragma unroll
        for (int j = 0; j < 4; j++) sc[i][j] = 0.f;

    #pragma unroll 4
    for (int c = 0; c < CC; c++) {
        float4 q0 = *(const float4*)&Qs[c * 128 + ty * 8];
        float4 q1 = *(const float4*)&Qs[c * 128 + ty * 8 + 4];
        float4 kv = *(const float4*)&Ks[c * 72 + tx * 4];
        float qv[8] = {q0.x,q0.y,q0.z,q0.w,q1.x,q1.y,q1.z,q1.w};
        float k4[4] = {kv.x,kv.y,kv.z,kv.w};
        #pragma unroll
        for (int i = 0; i < 8; i++)
            #pragma unroll
            for (int j = 0; j < 4; j++)
                sc[i][j] += qv[i] * k4[j];
    }
    float ssv = *ss_p, psv = *ps_p;
    #pragma unroll
    for (int i = 0; i < 8; i++)
        #pragma unroll
        for (int j = 0; j < 4; j++)
            sc[i][j] = sc[i][j] * ssv
                     + basis[(tx * 4 + j) * FF + fb + ty * 8 + i] * psv;
    __syncthreads();   // Qs now dead; safe to overlay Vt/Wsm

    // softmax over k (64 values split across 16 tx threads x 4 each)
    float w[8][4];
    #pragma unroll
    for (int i = 0; i < 8; i++) {
        float m = fmaxf(fmaxf(sc[i][0], sc[i][1]), fmaxf(sc[i][2], sc[i][3]));
        #pragma unroll
        for (int off = 8; off >= 1; off >>= 1)
            m = fmaxf(m, __shfl_xor_sync(0xffffffffu, m, off));
        float e0 = __expf(sc[i][0] - m);
        float e1 = __expf(sc[i][1] - m);
        float e2 = __expf(sc[i][2] - m);
        float e3 = __expf(sc[i][3] - m);
        float s = e0 + e1 + e2 + e3;
        #pragma unroll
        for (int off = 8; off >= 1; off >>= 1)
            s += __shfl_xor_sync(0xffffffffu, s, off);
        float inv = 1.0f / s;
        w[i][0] = e0 * inv; w[i][1] = e1 * inv;
        w[i][2] = e2 * inv; w[i][3] = e3 * inv;
    }
    #pragma unroll
    for (int i = 0; i < 8; i++)
        #pragma unroll
        for (int j = 0; j < 4; j++)
            Wsm[(tx * 4 + j) * 136 + ty * 8 + i] = w[i][j];

    const float* vb = vmat + (size_t)b * CC * S_LAT + t * KK;
    #pragma unroll
    for (int it = 0; it < 8; it++) {
        int idx = tid + it * 256;
        int c = idx >> 4, kq = idx & 15;
        float4 v = *(const float4*)(vb + (size_t)c * S_LAT + kq * 4);
        Vt[(kq * 4 + 0) * 136 + c] = v.x;
        Vt[(kq * 4 + 1) * 136 + c] = v.y;
        Vt[(kq * 4 + 2) * 136 + c] = v.z;
        Vt[(kq * 4 + 3) * 136 + c] = v.w;
    }
    __syncthreads();

    // phase 2: att tile [128 c][128 f], micro 8c x 8f
    float ac[8][8];
    #pragma unroll
    for (int i = 0; i < 8; i++)
        #pragma unroll
        for (int j = 0; j < 8; j++) ac[i][j] = 0.f;

    #pragma unroll 4
    for (int k = 0; k < KK; k++) {
        float4 v0 = *(const float4*)&Vt[k * 136 + ty * 8];
        float4 v1 = *(const float4*)&Vt[k * 136 + ty * 8 + 4];
        float4 w0 = *(const float4*)&Wsm[k * 136 + tx * 8];
        float4 w1 = *(const float4*)&Wsm[k * 136 + tx * 8 + 4];
        float vv[8] = {v0.x,v0.y,v0.z,v0.w,v1.x,v1.y,v1.z,v1.w};
        float ww[8] = {w0.x,w0.y,w0.z,w0.w,w1.x,w1.y,w1.z,w1.w};
        #pragma unroll
        for (int i = 0; i < 8; i++)
            #pragma unroll
            for (int j = 0; j < 8; j++)
                ac[i][j] += vv[i] * ww[j];
    }
    #pragma unroll
    for (int i = 0; i < 8; i++) {
        float* orow = att + (((size_t)b * CC + ty * 8 + i) * TT + t) * FF + fb + tx * 8;
        *(float4*)(orow + 0) = make_float4(ac[i][0], ac[i][1], ac[i][2], ac[i][3]);
        *(float4*)(orow + 4) = make_float4(ac[i][4], ac[i][5], ac[i][6], ac[i][7]);
    }
}

// ---------------- host ----------------
extern "C" void kernel_launch(void* const* d_in, const int* in_sizes, int n_in,
                              void* d_out, int out_size)
{
    const float* latent     = (const float*)d_in[0];
    const float* side       = (const float*)d_in[1];
    const float* basis      = (const float*)d_in[2];
    const float* lp_gamma   = (const float*)d_in[3];
    const float* lp_w       = (const float*)d_in[4];
    const float* lp_b       = (const float*)d_in[5];
    const float* qn_gamma   = (const float*)d_in[6];
    const float* qmlp_in_w  = (const float*)d_in[7];
    const float* qmlp_in_b  = (const float*)d_in[8];
    const float* qmlp_out_w = (const float*)d_in[9];
    const float* qmlp_out_b = (const float*)d_in[10];
    const float* q_w        = (const float*)d_in[11];
    const float* q_b        = (const float*)d_in[12];
    const float* k_w        = (const float*)d_in[13];
    const float* k_b        = (const float*)d_in[14];
    const float* v_w        = (const float*)d_in[15];
    const float* v_b        = (const float*)d_in[16];
    const float* o_w        = (const float*)d_in[17];
    const float* o_b        = (const float*)d_in[18];
    const float* ffn_gamma  = (const float*)d_in[19];
    const float* ffn_in_w   = (const float*)d_in[20];
    const float* ffn_in_b   = (const float*)d_in[21];
    const float* ffn_out_w  = (const float*)d_in[22];
    const float* ffn_out_b  = (const float*)d_in[23];
    const float* score_sc   = (const float*)d_in[24];
    const float* prior_sc   = (const float*)d_in[25];
    const float* qskip_sc   = (const float*)d_in[26];
    float* out = (float*)d_out;

    float *buf1, *buf2, *buf3, *lh, *kmat, *vmat;
    cudaGetSymbolAddress((void**)&buf1, g_buf1);
    cudaGetSymbolAddress((void**)&buf2, g_buf2);
    cudaGetSymbolAddress((void**)&buf3, g_buf3);
    cudaGetSymbolAddress((void**)&lh,   g_lh);
    cudaGetSymbolAddress((void**)&kmat, g_k);
    cudaGetSymbolAddress((void**)&vmat, g_v);

    cudaFuncSetAttribute(attn_kernel,
                         cudaFuncAttributeMaxDynamicSharedMemorySize, ATT_SMEM_BYTES);

    dim3 blk(256);

    // ---- latent path ----
    rmsnorm_kernel<<<dim3(S_LAT/1024, BB), blk>>>(latent, lp_gamma, buf1, S_LAT);
    gemm128_kernel<1,0><<<dim3(S_LAT/128, BB), blk>>>(buf1, lp_w, lp_b, lh, nullptr, nullptr, S_LAT);
    gemm128_kernel<0,0><<<dim3(S_LAT/128, BB), blk>>>(lh, k_w, k_b, kmat, nullptr, nullptr, S_LAT);
    gemm128_kernel<0,0><<<dim3(S_LAT/128, BB), blk>>>(lh, v_w, v_b, vmat, nullptr, nullptr, S_LAT);

    // ---- side / query path ----
    rmsnorm_kernel<<<dim3(S_SIDE/1024, BB), blk>>>(side, qn_gamma, buf1, S_SIDE);
    gemm_glu_kernel<<<dim3(S_SIDE/64, BB), blk>>>(buf1, qmlp_in_w, qmlp_in_b, buf2, S_SIDE);
    gemm128_kernel<0,0><<<dim3(S_SIDE/128, BB), blk>>>(buf2, qmlp_out_w, qmlp_out_b, buf3, nullptr, nullptr, S_SIDE);
    gemm128_kernel<0,0><<<dim3(S_SIDE/128, BB), blk>>>(buf3, q_w, q_b, buf2, nullptr, nullptr, S_SIDE);

    // ---- attention ----
    attn_kernel<<<dim3(FF/128, TT, BB), blk, ATT_SMEM_BYTES>>>(
        buf2, kmat, vmat, basis, score_sc, prior_sc, buf1);

    // ---- output projection + query skip -> hidden (d_out) ----
    gemm128_kernel<0,1><<<dim3(S_SIDE/128, BB), blk>>>(buf1, o_w, o_b, out, buf3, qskip_sc, S_SIDE);

    // ---- FFN (residual into d_out) ----
    rmsnorm_kernel<<<dim3(S_SIDE/1024, BB), blk>>>(out, ffn_gamma, buf1, S_SIDE);
    gemm_glu_kernel<<<dim3(S_SIDE/64, BB), blk>>>(buf1, ffn_in_w, ffn_in_b, buf2, S_SIDE);
    gemm128_kernel<0,2><<<dim3(S_SIDE/128, BB), blk>>>(buf2, ffn_out_w, ffn_out_b, out, nullptr, nullptr, S_SIDE);
}

// round 2
// speedup vs baseline: 1.0644x; 1.0644x over previous
#include <cuda_runtime.h>
#include <cuda_bf16.h>

#define BB 8
#define CC 128
#define TT 128
#define FF 512
#define KK 64
#define S_SIDE (TT*FF)   /* 65536 */
#define S_LAT  (TT*KK)   /* 8192  */

// ---------------- scratch (static device globals; no allocation) ----------------
__device__ float g_buf1[BB*CC*S_SIDE];   // att
__device__ float g_buf2[BB*CC*S_SIDE];   // glu out / q / glu2 out
__device__ float g_buf3[BB*CC*S_SIDE];   // query_h
__device__ float g_rms [BB*S_SIDE];      // inv-rms per (b,s)
__device__ float g_lh [BB*CC*S_LAT];
__device__ float g_k  [BB*CC*S_LAT];
__device__ float g_v  [BB*CC*S_LAT];

typedef unsigned long long u64;

__device__ __forceinline__ float silu_f(float x) {
    return x / (1.0f + __expf(-x));
}
__device__ __forceinline__ u64 dup2(float v) {
    u64 r;
    asm("mov.b64 %0, {%1, %2};" : "=l"(r) : "f"(v), "f"(v));
    return r;
}
__device__ __forceinline__ void fma2(u64& d, u64 a, u64 b) {
    asm("fma.rn.f32x2 %0, %1, %2, %0;" : "+l"(d) : "l"(a), "l"(b));
}
__device__ __forceinline__ float2 unpack2(u64 v) {
    float2 r;
    asm("mov.b64 {%0, %1}, %2;" : "=f"(r.x), "=f"(r.y) : "l"(v));
    return r;
}

// ---------------- inv-RMS over channel dim: R[b,s] = rsqrt(mean_c X^2 + eps) ----------------
__global__ __launch_bounds__(256)
void rms_scale_kernel(const float* __restrict__ X, float* __restrict__ R, int S)
{
    int b = blockIdx.y;
    int s = blockIdx.x * 1024 + threadIdx.x * 4;
    const float* xb = X + (size_t)b * CC * S + s;

    float4 acc = make_float4(0.f, 0.f, 0.f, 0.f);
    #pragma unroll 4
    for (int c = 0; c < CC; c++) {
        float4 v = *(const float4*)(xb + (size_t)c * S);
        acc.x += v.x * v.x; acc.y += v.y * v.y;
        acc.z += v.z * v.z; acc.w += v.w * v.w;
    }
    const float inv = 1.0f / CC;
    float4 r;
    r.x = rsqrtf(acc.x * inv + 1e-6f);
    r.y = rsqrtf(acc.y * inv + 1e-6f);
    r.z = rsqrtf(acc.z * inv + 1e-6f);
    r.w = rsqrtf(acc.w * inv + 1e-6f);
    *(float4*)(R + (size_t)b * S + s) = r;
}

// ---------------- GEMM: Y[b][o,s] = epi(sum_c W'[o,c] * X'[b][c,s] + bias[o]) ----------------
// NORM: X' = X * r[s], W' = W * gamma[c].  ACT: 0 none, 1 silu.
// EPI: 0 none, 1 += (*sc_p)*extra, 2 += Y(existing)
template<int NORM, int ACT, int EPI>
__global__ __launch_bounds__(256)
void gemm128_kernel(const float* __restrict__ X, const float* __restrict__ W,
                    const float* __restrict__ bias, float* __restrict__ Y,
                    const float* __restrict__ extra, const float* __restrict__ sc_p,
                    const float* __restrict__ rms, const float* __restrict__ gamma, int S)
{
    __shared__ float Ws[16][136];
    __shared__ float Xs[16][128];
    int b  = blockIdx.y;
    int s0 = blockIdx.x * 128;
    int tid = threadIdx.x;
    int tx = tid & 15, ty = tid >> 4;   // tx: s-group of 8, ty: o-pair-group (8 rows)
    const float* Xb = X + (size_t)b * CC * S;

    u64 acc2[4][8];   // pairs over o (i), 8 s-columns (j)
    #pragma unroll
    for (int i = 0; i < 4; i++)
        #pragma unroll
        for (int j = 0; j < 8; j++) acc2[i][j] = 0ull;

    for (int kk = 0; kk < CC; kk += 16) {
        #pragma unroll
        for (int it = 0; it < 2; it++) {
            int t = tid + it * 256;          // 0..511
            int o = t >> 2, cq = t & 3;
            float4 w4 = *(const float4*)(W + o * CC + kk + cq * 4);
            if (NORM) {
                float4 g4 = *(const float4*)(gamma + kk + cq * 4);
                w4.x *= g4.x; w4.y *= g4.y; w4.z *= g4.z; w4.w *= g4.w;
            }
            Ws[cq*4+0][o] = w4.x; Ws[cq*4+1][o] = w4.y;
            Ws[cq*4+2][o] = w4.z; Ws[cq*4+3][o] = w4.w;
        }
        #pragma unroll
        for (int it = 0; it < 2; it++) {
            int t = tid + it * 256;
            int k = t >> 5, sq = t & 31;
            float4 x4 = *(const float4*)(Xb + (size_t)(kk + k) * S + s0 + sq * 4);
            if (NORM) {
                float4 r4 = *(const float4*)(rms + (size_t)b * S + s0 + sq * 4);
                x4.x *= r4.x; x4.y *= r4.y; x4.z *= r4.z; x4.w *= r4.w;
            }
            *(float4*)&Xs[k][sq * 4] = x4;
        }
        __syncthreads();
        #pragma unroll
        for (int k = 0; k < 16; k++) {
            u64 wp[4];
            #pragma unroll
            for (int i = 0; i < 4; i++)
                wp[i] = *(const u64*)&Ws[k][ty * 8 + 2 * i];
            float4 x0 = *(const float4*)&Xs[k][tx * 8];
            float4 x1 = *(const float4*)&Xs[k][tx * 8 + 4];
            u64 xb8[8] = {dup2(x0.x),dup2(x0.y),dup2(x0.z),dup2(x0.w),
                          dup2(x1.x),dup2(x1.y),dup2(x1.z),dup2(x1.w)};
            #pragma unroll
            for (int i = 0; i < 4; i++)
                #pragma unroll
                for (int j = 0; j < 8; j++)
                    fma2(acc2[i][j], wp[i], xb8[j]);
        }
        __syncthreads();
    }

    float scl = (EPI == 1) ? *sc_p : 0.f;
    #pragma unroll
    for (int i = 0; i < 4; i++) {
        int o0 = ty * 8 + 2 * i;
        float bv0 = bias[o0], bv1 = bias[o0 + 1];
        float r0[8], r1[8];
        #pragma unroll
        for (int j = 0; j < 8; j++) {
            float2 p = unpack2(acc2[i][j]);
            r0[j] = p.x + bv0;
            r1[j] = p.y + bv1;
        }
        #pragma unroll
        for (int half = 0; half < 2; half++) {
            int o = o0 + half;
            float* rr = half ? r1 : r0;
            float* yrow = Y + ((size_t)b * CC + o) * S + s0 + tx * 8;
            const float* erow = (EPI == 1) ? (extra + ((size_t)b * CC + o) * S + s0 + tx * 8) : nullptr;
            float out[8];
            #pragma unroll
            for (int j = 0; j < 8; j++) {
                float v = rr[j];
                if (ACT == 1) v = silu_f(v);
                if (EPI == 1) v += scl * erow[j];
                if (EPI == 2) v += yrow[j];
                out[j] = v;
            }
            *(float4*)(yrow + 0) = make_float4(out[0], out[1], out[2], out[3]);
            *(float4*)(yrow + 4) = make_float4(out[4], out[5], out[6], out[7]);
        }
    }
}

// ---------------- Dual GEMM GLU: U = (Wa X' + ba) * silu(Wg X' + bg) ----------------
// W: [2C, C]; NORM folds rms/gamma as above. Tile: 128 o x 64 s.
template<int NORM>
__global__ __launch_bounds__(256)
void gemm_glu_kernel(const float* __restrict__ X, const float* __restrict__ W,
                     const float* __restrict__ bias, float* __restrict__ Y,
                     const float* __restrict__ rms, const float* __restrict__ gamma, int S)
{
    __shared__ float Wa[16][136];
    __shared__ float Wg[16][136];
    __shared__ float Xs[16][64];
    int b  = blockIdx.y;
    int s0 = blockIdx.x * 64;
    int tid = threadIdx.x;
    int tx = tid & 7, ty = tid >> 3;    // tx: s-group of 8 (64 s), ty: o-group of 4 (128 o)
    const float* Xb = X + (size_t)b * CC * S;

    u64 a1[2][8], a2[2][8];             // o-pairs (2 pairs = 4 rows) x 8 s
    #pragma unroll
    for (int i = 0; i < 2; i++)
        #pragma unroll
        for (int j = 0; j < 8; j++) { a1[i][j] = 0ull; a2[i][j] = 0ull; }

    for (int kk = 0; kk < CC; kk += 16) {
        #pragma unroll
        for (int it = 0; it < 2; it++) {
            int t = tid + it * 256;
            int o = t >> 2, cq = t & 3;
            float4 g4;
            if (NORM) g4 = *(const float4*)(gamma + kk + cq * 4);
            float4 w4 = *(const float4*)(W + o * CC + kk + cq * 4);
            if (NORM) { w4.x *= g4.x; w4.y *= g4.y; w4.z *= g4.z; w4.w *= g4.w; }
            Wa[cq*4+0][o] = w4.x; Wa[cq*4+1][o] = w4.y;
            Wa[cq*4+2][o] = w4.z; Wa[cq*4+3][o] = w4.w;
            float4 h4 = *(const float4*)(W + (o + CC) * CC + kk + cq * 4);
            if (NORM) { h4.x *= g4.x; h4.y *= g4.y; h4.z *= g4.z; h4.w *= g4.w; }
            Wg[cq*4+0][o] = h4.x; Wg[cq*4+1][o] = h4.y;
            Wg[cq*4+2][o] = h4.z; Wg[cq*4+3][o] = h4.w;
        }
        {
            int k = tid >> 4, sq = tid & 15;
            float4 x4 = *(const float4*)(Xb + (size_t)(kk + k) * S + s0 + sq * 4);
            if (NORM) {
                float4 r4 = *(const float4*)(rms + (size_t)b * S + s0 + sq * 4);
                x4.x *= r4.x; x4.y *= r4.y; x4.z *= r4.z; x4.w *= r4.w;
            }
            *(float4*)&Xs[k][sq * 4] = x4;
        }
        __syncthreads();
        #pragma unroll
        for (int k = 0; k < 16; k++) {
            u64 wap[2], wgp[2];
            #pragma unroll
            for (int i = 0; i < 2; i++) {
                wap[i] = *(const u64*)&Wa[k][ty * 4 + 2 * i];
                wgp[i] = *(const u64*)&Wg[k][ty * 4 + 2 * i];
            }
            float4 x0 = *(const float4*)&Xs[k][tx * 8];
            float4 x1 = *(const float4*)&Xs[k][tx * 8 + 4];
            u64 xb8[8] = {dup2(x0.x),dup2(x0.y),dup2(x0.z),dup2(x0.w),
                          dup2(x1.x),dup2(x1.y),dup2(x1.z),dup2(x1.w)};
            #pragma unroll
            for (int i = 0; i < 2; i++)
                #pragma unroll
                for (int j = 0; j < 8; j++) {
                    fma2(a1[i][j], wap[i], xb8[j]);
                    fma2(a2[i][j], wgp[i], xb8[j]);
                }
        }
        __syncthreads();
    }

    #pragma unroll
    for (int i = 0; i < 2; i++) {
        int o0 = ty * 4 + 2 * i;
        float ba0 = bias[o0], ba1 = bias[o0 + 1];
        float bg0 = bias[CC + o0], bg1 = bias[CC + o0 + 1];
        float v0[8], v1[8];
        #pragma unroll
        for (int j = 0; j < 8; j++) {
            float2 pa = unpack2(a1[i][j]);
            float2 pg = unpack2(a2[i][j]);
            v0[j] = (pa.x + ba0) * silu_f(pg.x + bg0);
            v1[j] = (pa.y + ba1) * silu_f(pg.y + bg1);
        }
        #pragma unroll
        for (int half = 0; half < 2; half++) {
            int o = o0 + half;
            float* vv = half ? v1 : v0;
            float* yrow = Y + ((size_t)b * CC + o) * S + s0 + tx * 8;
            *(float4*)(yrow + 0) = make_float4(vv[0], vv[1], vv[2], vv[3]);
            *(float4*)(yrow + 4) = make_float4(vv[4], vv[5], vv[6], vv[7]);
        }
    }
}

// ---------------- Attention: per (b, t, 128-wide f chunk) ----------------
#define ATT_SMEM_FLOATS (128*72 + 2*64*136)
#define ATT_SMEM_BYTES  (ATT_SMEM_FLOATS * 4)

__global__ __launch_bounds__(256)
void attn_kernel(const float* __restrict__ q, const float* __restrict__ kmat,
                 const float* __restrict__ vmat, const float* __restrict__ basis,
                 const float* __restrict__ ss_p, const float* __restrict__ ps_p,
                 float* __restrict__ att)
{
    extern __shared__ float sm[];
    float* Ks  = sm;                 // [128][72]
    float* Qs  = sm + 128 * 72;      // [128][128]  (overlaid after phase 1)
    float* Vt  = Qs;                 // [64][136]
    float* Wsm = Qs + 64 * 136;      // [64][136]

    int fb = blockIdx.x * 128;
    int t  = blockIdx.y;
    int b  = blockIdx.z;
    int tid = threadIdx.x;
    int tx = tid & 15, ty = tid >> 4;

    const float* kb = kmat + (size_t)b * CC * S_LAT + t * KK;
    #pragma unroll
    for (int it = 0; it < 8; it++) {
        int idx = tid + it * 256;
        int c = idx >> 4, kq = idx & 15;
        float4 v = *(const float4*)(kb + (size_t)c * S_LAT + kq * 4);
        *(float4*)&Ks[c * 72 + kq * 4] = v;
    }
    const float* qb = q + (size_t)b * CC * S_SIDE + t * FF + fb;
    #pragma unroll
    for (int it = 0; it < 16; it++) {
        int idx = tid + it * 256;
        int c = idx >> 5, fq = idx & 31;
        float4 v = *(const float4*)(qb + (size_t)c * S_SIDE + fq * 4);
        *(float4*)&Qs[c * 128 + fq * 4] = v;
    }
    __syncthreads();

    // phase 1: scores tile [128 f][64 k], micro 8f x 4k (2 k-pairs)
    u64 sc2[8][2];
    #pragma unroll
    for (int i = 0; i < 8; i++) { sc2[i][0] = 0ull; sc2[i][1] = 0ull; }

    #pragma unroll 4
    for (int c = 0; c < CC; c++) {
        u64 kp0 = *(const u64*)&Ks[c * 72 + tx * 4];
        u64 kp1 = *(const u64*)&Ks[c * 72 + tx * 4 + 2];
        float4 q0 = *(const float4*)&Qs[c * 128 + ty * 8];
        float4 q1 = *(const float4*)&Qs[c * 128 + ty * 8 + 4];
        u64 qd[8] = {dup2(q0.x),dup2(q0.y),dup2(q0.z),dup2(q0.w),
                     dup2(q1.x),dup2(q1.y),dup2(q1.z),dup2(q1.w)};
        #pragma unroll
        for (int i = 0; i < 8; i++) {
            fma2(sc2[i][0], qd[i], kp0);
            fma2(sc2[i][1], qd[i], kp1);
        }
    }
    float sc[8][4];
    #pragma unroll
    for (int i = 0; i < 8; i++) {
        float2 p0 = unpack2(sc2[i][0]);
        float2 p1 = unpack2(sc2[i][1]);
        sc[i][0] = p0.x; sc[i][1] = p0.y; sc[i][2] = p1.x; sc[i][3] = p1.y;
    }
    float ssv = *ss_p, psv = *ps_p;
    #pragma unroll
    for (int i = 0; i < 8; i++)
        #pragma unroll
        for (int j = 0; j < 4; j++)
            sc[i][j] = sc[i][j] * ssv
                     + basis[(tx * 4 + j) * FF + fb + ty * 8 + i] * psv;
    __syncthreads();   // Qs now dead

    // softmax over k (64 values split across 16 tx threads x 4 each)
    float w[8][4];
    #pragma unroll
    for (int i = 0; i < 8; i++) {
        float m = fmaxf(fmaxf(sc[i][0], sc[i][1]), fmaxf(sc[i][2], sc[i][3]));
        #pragma unroll
        for (int off = 8; off >= 1; off >>= 1)
            m = fmaxf(m, __shfl_xor_sync(0xffffffffu, m, off));
        float e0 = __expf(sc[i][0] - m);
        float e1 = __expf(sc[i][1] - m);
        float e2 = __expf(sc[i][2] - m);
        float e3 = __expf(sc[i][3] - m);
        float s = e0 + e1 + e2 + e3;
        #pragma unroll
        for (int off = 8; off >= 1; off >>= 1)
            s += __shfl_xor_sync(0xffffffffu, s, off);
        float inv = 1.0f / s;
        w[i][0] = e0 * inv; w[i][1] = e1 * inv;
        w[i][2] = e2 * inv; w[i][3] = e3 * inv;
    }
    #pragma unroll
    for (int i = 0; i < 8; i++)
        #pragma unroll
        for (int j = 0; j < 4; j++)
            Wsm[(tx * 4 + j) * 136 + ty * 8 + i] = w[i][j];

    const float* vb = vmat + (size_t)b * CC * S_LAT + t * KK;
    #pragma unroll
    for (int it = 0; it < 8; it++) {
        int idx = tid + it * 256;
        int c = idx >> 4, kq = idx & 15;
        float4 v = *(const float4*)(vb + (size_t)c * S_LAT + kq * 4);
        Vt[(kq * 4 + 0) * 136 + c] = v.x;
        Vt[(kq * 4 + 1) * 136 + c] = v.y;
        Vt[(kq * 4 + 2) * 136 + c] = v.z;
        Vt[(kq * 4 + 3) * 136 + c] = v.w;
    }
    __syncthreads();

    // phase 2: att tile [128 c][128 f], c-pairs x 8 f
    u64 ac2[4][8];
    #pragma unroll
    for (int i = 0; i < 4; i++)
        #pragma unroll
        for (int j = 0; j < 8; j++) ac2[i][j] = 0ull;

    #pragma unroll 4
    for (int k = 0; k < KK; k++) {
        u64 vp[4];
        #pragma unroll
        for (int i = 0; i < 4; i++)
            vp[i] = *(const u64*)&Vt[k * 136 + ty * 8 + 2 * i];
        float4 w0 = *(const float4*)&Wsm[k * 136 + tx * 8];
        float4 w1 = *(const float4*)&Wsm[k * 136 + tx * 8 + 4];
        u64 wd[8] = {dup2(w0.x),dup2(w0.y),dup2(w0.z),dup2(w0.w),
                     dup2(w1.x),dup2(w1.y),dup2(w1.z),dup2(w1.w)};
        #pragma unroll
        for (int i = 0; i < 4; i++)
            #pragma unroll
            for (int j = 0; j < 8; j++)
                fma2(ac2[i][j], vp[i], wd[j]);
    }
    #pragma unroll
    for (int i = 0; i < 4; i++) {
        float r0[8], r1[8];
        #pragma unroll
        for (int j = 0; j < 8; j++) {
            float2 p = unpack2(ac2[i][j]);
            r0[j] = p.x; r1[j] = p.y;
        }
        #pragma unroll
        for (int half = 0; half < 2; half++) {
            int c = ty * 8 + 2 * i + half;
            float* rr = half ? r1 : r0;
            float* orow = att + (((size_t)b * CC + c) * TT + t) * FF + fb + tx * 8;
            *(float4*)(orow + 0) = make_float4(rr[0], rr[1], rr[2], rr[3]);
            *(float4*)(orow + 4) = make_float4(rr[4], rr[5], rr[6], rr[7]);
        }
    }
}

// ---------------- host ----------------
extern "C" void kernel_launch(void* const* d_in, const int* in_sizes, int n_in,
                              void* d_out, int out_size)
{
    const float* latent     = (const float*)d_in[0];
    const float* side       = (const float*)d_in[1];
    const float* basis      = (const float*)d_in[2];
    const float* lp_gamma   = (const float*)d_in[3];
    const float* lp_w       = (const float*)d_in[4];
    const float* lp_b       = (const float*)d_in[5];
    const float* qn_gamma   = (const float*)d_in[6];
    const float* qmlp_in_w  = (const float*)d_in[7];
    const float* qmlp_in_b  = (const float*)d_in[8];
    const float* qmlp_out_w = (const float*)d_in[9];
    const float* qmlp_out_b = (const float*)d_in[10];
    const float* q_w        = (const float*)d_in[11];
    const float* q_b        = (const float*)d_in[12];
    const float* k_w        = (const float*)d_in[13];
    const float* k_b        = (const float*)d_in[14];
    const float* v_w        = (const float*)d_in[15];
    const float* v_b        = (const float*)d_in[16];
    const float* o_w        = (const float*)d_in[17];
    const float* o_b        = (const float*)d_in[18];
    const float* ffn_gamma  = (const float*)d_in[19];
    const float* ffn_in_w   = (const float*)d_in[20];
    const float* ffn_in_b   = (const float*)d_in[21];
    const float* ffn_out_w  = (const float*)d_in[22];
    const float* ffn_out_b  = (const float*)d_in[23];
    const float* score_sc   = (const float*)d_in[24];
    const float* prior_sc   = (const float*)d_in[25];
    const float* qskip_sc   = (const float*)d_in[26];
    float* out = (float*)d_out;

    float *buf1, *buf2, *buf3, *rmsb, *lh, *kmat, *vmat;
    cudaGetSymbolAddress((void**)&buf1, g_buf1);
    cudaGetSymbolAddress((void**)&buf2, g_buf2);
    cudaGetSymbolAddress((void**)&buf3, g_buf3);
    cudaGetSymbolAddress((void**)&rmsb, g_rms);
    cudaGetSymbolAddress((void**)&lh,   g_lh);
    cudaGetSymbolAddress((void**)&kmat, g_k);
    cudaGetSymbolAddress((void**)&vmat, g_v);

    cudaFuncSetAttribute(attn_kernel,
                         cudaFuncAttributeMaxDynamicSharedMemorySize, ATT_SMEM_BYTES);

    dim3 blk(256);

    // ---- latent path: fused rmsnorm + conv + silu, then k/v ----
    rms_scale_kernel<<<dim3(S_LAT/1024, BB), blk>>>(latent, rmsb, S_LAT);
    gemm128_kernel<1,1,0><<<dim3(S_LAT/128, BB), blk>>>(latent, lp_w, lp_b, lh, nullptr, nullptr, rmsb, lp_gamma, S_LAT);
    gemm128_kernel<0,0,0><<<dim3(S_LAT/128, BB), blk>>>(lh, k_w, k_b, kmat, nullptr, nullptr, nullptr, nullptr, S_LAT);
    gemm128_kernel<0,0,0><<<dim3(S_LAT/128, BB), blk>>>(lh, v_w, v_b, vmat, nullptr, nullptr, nullptr, nullptr, S_LAT);

    // ---- side / query path ----
    rms_scale_kernel<<<dim3(S_SIDE/1024, BB), blk>>>(side, rmsb, S_SIDE);
    gemm_glu_kernel<1><<<dim3(S_SIDE/64, BB), blk>>>(side, qmlp_in_w, qmlp_in_b, buf2, rmsb, qn_gamma, S_SIDE);
    gemm128_kernel<0,0,0><<<dim3(S_SIDE/128, BB), blk>>>(buf2, qmlp_out_w, qmlp_out_b, buf3, nullptr, nullptr, nullptr, nullptr, S_SIDE);
    gemm128_kernel<0,0,0><<<dim3(S_SIDE/128, BB), blk>>>(buf3, q_w, q_b, buf2, nullptr, nullptr, nullptr, nullptr, S_SIDE);

    // ---- attention ----
    attn_kernel<<<dim3(FF/128, TT, BB), blk, ATT_SMEM_BYTES>>>(
        buf2, kmat, vmat, basis, score_sc, prior_sc, buf1);

    // ---- output projection + query skip -> hidden (d_out) ----
    gemm128_kernel<0,0,1><<<dim3(S_SIDE/128, BB), blk>>>(buf1, o_w, o_b, out, buf3, qskip_sc, nullptr, nullptr, S_SIDE);

    // ---- FFN (residual into d_out) ----
    rms_scale_kernel<<<dim3(S_SIDE/1024, BB), blk>>>(out, rmsb, S_SIDE);
    gemm_glu_kernel<1><<<dim3(S_SIDE/64, BB), blk>>>(out, ffn_in_w, ffn_in_b, buf2, rmsb, ffn_gamma, S_SIDE);
    gemm128_kernel<0,0,2><<<dim3(S_SIDE/128, BB), blk>>>(buf2, ffn_out_w, ffn_out_b, out, nullptr, nullptr, nullptr, nullptr, S_SIDE);
}

// round 6
// speedup vs baseline: 1.2988x; 1.2203x over previous
#include <cuda_runtime.h>
#include <cuda_bf16.h>
#include <cstdint>

#define BB 8
#define CC 128
#define TT 128
#define FF 512
#define KK 64
#define S_SIDE (TT*FF)
#define S_LAT  (TT*KK)

typedef unsigned long long u64;
typedef unsigned int u32;
typedef unsigned short u16;

__device__ float g_buf1[BB*CC*S_SIDE];
__device__ float g_buf2[BB*CC*S_SIDE];
__device__ float g_buf3[BB*CC*S_SIDE];
__device__ float g_rms [BB*S_SIDE];
__device__ float g_lh [BB*CC*S_LAT];
__device__ float g_k  [BB*CC*S_LAT];
__device__ float g_v  [BB*CC*S_LAT];

__device__ __forceinline__ float silu_f(float x) {
    return x / (1.0f + __expf(-x));
}
__device__ __forceinline__ u64 dup2(float v) {
    u64 r; asm("mov.b64 %0, {%1, %2};" : "=l"(r) : "f"(v), "f"(v)); return r;
}
__device__ __forceinline__ void fma2(u64& d, u64 a, u64 b) {
    asm("fma.rn.f32x2 %0, %1, %2, %0;" : "+l"(d) : "l"(a), "l"(b));
}
__device__ __forceinline__ float2 unpack2(u64 v) {
    float2 r; asm("mov.b64 {%0, %1}, %2;" : "=f"(r.x), "=f"(r.y) : "l"(v)); return r;
}
__device__ __forceinline__ u32 smem_u32(const void* p) {
    u32 a;
    asm("{ .reg .u64 t; cvta.to.shared.u64 t, %1; cvt.u32.u64 %0, t; }" : "=r"(a) : "l"(p));
    return a;
}

// ---------------- mma.sync helpers (baseline PTX, valid on sm_103) ----------------
__device__ __forceinline__ void ldsm4(u32* r, u32 addr) {
    asm volatile("ldmatrix.sync.aligned.m8n8.x4.shared.b16 {%0,%1,%2,%3}, [%4];"
                 : "=r"(r[0]), "=r"(r[1]), "=r"(r[2]), "=r"(r[3]) : "r"(addr));
}
__device__ __forceinline__ void mma16816(float* d, const u32* a, const u32* b) {
    asm volatile("mma.sync.aligned.m16n8k16.row.col.f32.bf16.bf16.f32 "
                 "{%0,%1,%2,%3}, {%4,%5,%6,%7}, {%8,%9}, {%0,%1,%2,%3};"
                 : "+f"(d[0]), "+f"(d[1]), "+f"(d[2]), "+f"(d[3])
                 : "r"(a[0]), "r"(a[1]), "r"(a[2]), "r"(a[3]), "r"(b[0]), "r"(b[1]));
}

// bf16 tiles: 128 rows x 128 cols, row stride 272 bytes (136 bf16).
// 272 mod 128 = 16 -> ldmatrix 8-row reads are bank-conflict-free.
#define TSTR  272
#define TILE_B (128*TSTR)

// fp32 -> bf16 hi/lo split; store 4 consecutive cols (8B each to hi and lo tile)
__device__ __forceinline__ void cvt_store4(char* smem, u32 hi_base, u32 lo_base,
                                           int row, int col, float4 x) {
    __nv_bfloat16 h0 = __float2bfloat16_rn(x.x); float r0 = x.x - __bfloat162float(h0);
    __nv_bfloat16 h1 = __float2bfloat16_rn(x.y); float r1 = x.y - __bfloat162float(h1);
    __nv_bfloat16 h2 = __float2bfloat16_rn(x.z); float r2 = x.z - __bfloat162float(h2);
    __nv_bfloat16 h3 = __float2bfloat16_rn(x.w); float r3 = x.w - __bfloat162float(h3);
    __nv_bfloat16 l0 = __float2bfloat16_rn(r0);
    __nv_bfloat16 l1 = __float2bfloat16_rn(r1);
    __nv_bfloat16 l2 = __float2bfloat16_rn(r2);
    __nv_bfloat16 l3 = __float2bfloat16_rn(r3);
    u64 hv = (u64)*(u16*)&h0 | ((u64)*(u16*)&h1 << 16) | ((u64)*(u16*)&h2 << 32) | ((u64)*(u16*)&h3 << 48);
    u64 lv = (u64)*(u16*)&l0 | ((u64)*(u16*)&l1 << 16) | ((u64)*(u16*)&l2 << 32) | ((u64)*(u16*)&l3 << 48);
    u32 o = (u32)(row * TSTR + col * 2);
    *(u64*)(smem + hi_base + o) = hv;
    *(u64*)(smem + lo_base + o) = lv;
}

// ---------------- inv-RMS over channel dim ----------------
__global__ __launch_bounds__(256)
void rms_scale_kernel(const float* __restrict__ X, float* __restrict__ R, int S)
{
    int b = blockIdx.y;
    int s = blockIdx.x * 1024 + threadIdx.x * 4;
    const float* xb = X + (size_t)b * CC * S + s;
    float4 acc = make_float4(0.f, 0.f, 0.f, 0.f);
    #pragma unroll 4
    for (int c = 0; c < CC; c++) {
        float4 v = *(const float4*)(xb + (size_t)c * S);
        acc.x += v.x * v.x; acc.y += v.y * v.y;
        acc.z += v.z * v.z; acc.w += v.w * v.w;
    }
    const float inv = 1.0f / CC;
    float4 r;
    r.x = rsqrtf(acc.x * inv + 1e-6f);
    r.y = rsqrtf(acc.y * inv + 1e-6f);
    r.z = rsqrtf(acc.z * inv + 1e-6f);
    r.w = rsqrtf(acc.w * inv + 1e-6f);
    *(float4*)(R + (size_t)b * S + s) = r;
}

// ================= HMMA GEMM: Y[o,s] = epi(sum_c W'[o,c] X'[c,s] + bias[o]) =================
// smem: Ahi | Alo | Bhi | Blo, each 128x128 bf16 w/ 272B row stride
#define GT_AHI 0
#define GT_ALO (GT_AHI + TILE_B)
#define GT_BHI (GT_ALO + TILE_B)
#define GT_BLO (GT_BHI + TILE_B)
#define GT_SMEM (GT_BLO + TILE_B)

template<int NORM, int ACT, int EPI>
__global__ __launch_bounds__(256)
void gemm_mm(const float* __restrict__ X, const float* __restrict__ W,
             const float* __restrict__ bias, float* __restrict__ Y,
             const float* __restrict__ extra, const float* __restrict__ sc_p,
             const float* __restrict__ rms, const float* __restrict__ gamma, int S)
{
    extern __shared__ char sm[];
    u32 sb = smem_u32(sm);
    int tid = threadIdx.x;
    int wid = tid >> 5, lane = tid & 31;
    int b  = blockIdx.y;
    int s0 = blockIdx.x * 128;
    const float* Xb = X + (size_t)b * CC * S;

    // ---- stage A (weights 128x128, row=o col=c) ----
    #pragma unroll
    for (int i = 0; i < 16; i++) {
        int e4 = i * 256 + tid;
        int o = e4 >> 5, c0 = (e4 & 31) * 4;
        float4 w4 = *(const float4*)(W + o * CC + c0);
        if (NORM) {
            float4 g4 = *(const float4*)(gamma + c0);
            w4.x *= g4.x; w4.y *= g4.y; w4.z *= g4.z; w4.w *= g4.w;
        }
        cvt_store4(sm, GT_AHI, GT_ALO, o, c0, w4);
    }
    // ---- stage B (activations transposed: row=s col=c) ----
    {
        float rv[4];
        #pragma unroll
        for (int j = 0; j < 4; j++)
            rv[j] = NORM ? rms[(size_t)b * S + s0 + lane + j * 32] : 1.0f;
        #pragma unroll
        for (int i = 0; i < 16; i++) {
            int s = lane + (i & 3) * 32;
            int c0 = ((wid << 2) + (i >> 2)) * 4;
            float4 x4;
            x4.x = Xb[(size_t)(c0 + 0) * S + s0 + s];
            x4.y = Xb[(size_t)(c0 + 1) * S + s0 + s];
            x4.z = Xb[(size_t)(c0 + 2) * S + s0 + s];
            x4.w = Xb[(size_t)(c0 + 3) * S + s0 + s];
            if (NORM) {
                float r = rv[i & 3];
                x4.x *= r; x4.y *= r; x4.z *= r; x4.w *= r;
            }
            cvt_store4(sm, GT_BHI, GT_BLO, s, c0, x4);
        }
    }
    __syncthreads();

    // ---- warp tile: 32m x 64n ----
    int m_blk = (wid & 3) * 32;
    int n_blk = (wid >> 2) * 64;
    float acc[2][8][4];
    #pragma unroll
    for (int i = 0; i < 2; i++)
        #pragma unroll
        for (int j = 0; j < 8; j++)
            #pragma unroll
            for (int q = 0; q < 4; q++) acc[i][j][q] = 0.f;

    u32 a_row = (u32)(m_blk + (lane & 15));
    u32 a_koff = (u32)((lane >> 4) << 3);
    u32 b_row = (u32)((lane & 7) + ((lane >> 4) << 3));
    u32 b_koff = (u32)(((lane >> 3) & 1) << 3);

    const u32 abase[3] = {sb + GT_AHI, sb + GT_AHI, sb + GT_ALO};
    const u32 bbase[3] = {sb + GT_BHI, sb + GT_BLO, sb + GT_BHI};

    #pragma unroll
    for (int p = 0; p < 3; p++) {
        u32 ab = abase[p], bb = bbase[p];
        #pragma unroll
        for (int ks = 0; ks < 8; ks++) {
            int k0 = ks * 16;
            u32 af[2][4], bf[4][4];
            #pragma unroll
            for (int i = 0; i < 2; i++)
                ldsm4(af[i], ab + (a_row + i * 16) * TSTR + (k0 + a_koff) * 2);
            #pragma unroll
            for (int j = 0; j < 4; j++)
                ldsm4(bf[j], bb + (n_blk + j * 16 + b_row) * TSTR + (k0 + b_koff) * 2);
            #pragma unroll
            for (int i = 0; i < 2; i++)
                #pragma unroll
                for (int j = 0; j < 8; j++)
                    mma16816(acc[i][j], af[i], &bf[j >> 1][(j & 1) * 2]);
        }
    }

    // ---- epilogue ----
    float scl = (EPI == 1) ? *sc_p : 0.f;
    #pragma unroll
    for (int i = 0; i < 2; i++) {
        int r0 = m_blk + i * 16 + (lane >> 2);
        int r1 = r0 + 8;
        float bv0 = bias[r0], bv1 = bias[r1];
        #pragma unroll
        for (int j = 0; j < 8; j++) {
            int c = n_blk + j * 8 + (lane & 3) * 2;
            #pragma unroll
            for (int h = 0; h < 2; h++) {
                int o = h ? r1 : r0;
                float bv = h ? bv1 : bv0;
                float v0 = acc[i][j][h * 2 + 0] + bv;
                float v1 = acc[i][j][h * 2 + 1] + bv;
                if (ACT == 1) { v0 = silu_f(v0); v1 = silu_f(v1); }
                float* yp = Y + ((size_t)b * CC + o) * S + s0 + c;
                if (EPI == 1) {
                    const float* ep = extra + ((size_t)b * CC + o) * S + s0 + c;
                    v0 += scl * ep[0]; v1 += scl * ep[1];
                }
                if (EPI == 2) { v0 += yp[0]; v1 += yp[1]; }
                float2 ov; ov.x = v0; ov.y = v1;
                *(float2*)yp = ov;
            }
        }
    }
}

// ================= HMMA GLU: U = (Wa X' + ba) * silu(Wg X' + bg) =================
#define GL_AAHI 0
#define GL_AALO (GL_AAHI + TILE_B)
#define GL_AGHI (GL_AALO + TILE_B)
#define GL_AGLO (GL_AGHI + TILE_B)
#define GL_BHI  (GL_AGLO + TILE_B)
#define GL_BLO  (GL_BHI  + TILE_B)
#define GL_SMEM (GL_BLO  + TILE_B)

template<int NORM>
__global__ __launch_bounds__(256)
void glu_mm(const float* __restrict__ X, const float* __restrict__ W,
            const float* __restrict__ bias, float* __restrict__ Y,
            const float* __restrict__ rms, const float* __restrict__ gamma, int S)
{
    extern __shared__ char sm[];
    u32 sb = smem_u32(sm);
    int tid = threadIdx.x;
    int wid = tid >> 5, lane = tid & 31;
    int b  = blockIdx.y;
    int s0 = blockIdx.x * 128;
    const float* Xb = X + (size_t)b * CC * S;

    #pragma unroll
    for (int i = 0; i < 32; i++) {
        int e4 = i * 256 + tid;
        int o2 = e4 >> 5, c0 = (e4 & 31) * 4;
        float4 w4 = *(const float4*)(W + o2 * CC + c0);
        if (NORM) {
            float4 g4 = *(const float4*)(gamma + c0);
            w4.x *= g4.x; w4.y *= g4.y; w4.z *= g4.z; w4.w *= g4.w;
        }
        if (o2 < 128) cvt_store4(sm, GL_AAHI, GL_AALO, o2, c0, w4);
        else          cvt_store4(sm, GL_AGHI, GL_AGLO, o2 - 128, c0, w4);
    }
    {
        float rv[4];
        #pragma unroll
        for (int j = 0; j < 4; j++)
            rv[j] = NORM ? rms[(size_t)b * S + s0 + lane + j * 32] : 1.0f;
        #pragma unroll
        for (int i = 0; i < 16; i++) {
            int s = lane + (i & 3) * 32;
            int c0 = ((wid << 2) + (i >> 2)) * 4;
            float4 x4;
            x4.x = Xb[(size_t)(c0 + 0) * S + s0 + s];
            x4.y = Xb[(size_t)(c0 + 1) * S + s0 + s];
            x4.z = Xb[(size_t)(c0 + 2) * S + s0 + s];
            x4.w = Xb[(size_t)(c0 + 3) * S + s0 + s];
            if (NORM) {
                float r = rv[i & 3];
                x4.x *= r; x4.y *= r; x4.z *= r; x4.w *= r;
            }
            cvt_store4(sm, GL_BHI, GL_BLO, s, c0, x4);
        }
    }
    __syncthreads();

    int m_blk = (wid & 3) * 32;
    int n_blk = (wid >> 2) * 64;
    float acca[2][8][4], accg[2][8][4];
    #pragma unroll
    for (int i = 0; i < 2; i++)
        #pragma unroll
        for (int j = 0; j < 8; j++)
            #pragma unroll
            for (int q = 0; q < 4; q++) { acca[i][j][q] = 0.f; accg[i][j][q] = 0.f; }

    u32 a_row = (u32)(m_blk + (lane & 15));
    u32 a_koff = (u32)((lane >> 4) << 3);
    u32 b_row = (u32)((lane & 7) + ((lane >> 4) << 3));
    u32 b_koff = (u32)(((lane >> 3) & 1) << 3);

    const u32 aab[3] = {sb + GL_AAHI, sb + GL_AAHI, sb + GL_AALO};
    const u32 agb[3] = {sb + GL_AGHI, sb + GL_AGHI, sb + GL_AGLO};
    const u32 bbb[3] = {sb + GL_BHI,  sb + GL_BLO,  sb + GL_BHI };

    #pragma unroll
    for (int p = 0; p < 3; p++) {
        u32 aa = aab[p], ag = agb[p], bbs = bbb[p];
        #pragma unroll
        for (int ks = 0; ks < 8; ks++) {
            int k0 = ks * 16;
            u32 afa[2][4], afg[2][4], bf[4][4];
            #pragma unroll
            for (int i = 0; i < 2; i++) {
                ldsm4(afa[i], aa + (a_row + i * 16) * TSTR + (k0 + a_koff) * 2);
                ldsm4(afg[i], ag + (a_row + i * 16) * TSTR + (k0 + a_koff) * 2);
            }
            #pragma unroll
            for (int j = 0; j < 4; j++)
                ldsm4(bf[j], bbs + (n_blk + j * 16 + b_row) * TSTR + (k0 + b_koff) * 2);
            #pragma unroll
            for (int i = 0; i < 2; i++)
                #pragma unroll
                for (int j = 0; j < 8; j++) {
                    mma16816(acca[i][j], afa[i], &bf[j >> 1][(j & 1) * 2]);
                    mma16816(accg[i][j], afg[i], &bf[j >> 1][(j & 1) * 2]);
                }
        }
    }

    #pragma unroll
    for (int i = 0; i < 2; i++) {
        int r0 = m_blk + i * 16 + (lane >> 2);
        int r1 = r0 + 8;
        #pragma unroll
        for (int j = 0; j < 8; j++) {
            int c = n_blk + j * 8 + (lane & 3) * 2;
            #pragma unroll
            for (int h = 0; h < 2; h++) {
                int o = h ? r1 : r0;
                float ba = bias[o], bg = bias[CC + o];
                float a0 = acca[i][j][h * 2 + 0] + ba;
                float a1 = acca[i][j][h * 2 + 1] + ba;
                float g0 = accg[i][j][h * 2 + 0] + bg;
                float g1 = accg[i][j][h * 2 + 1] + bg;
                float2 ov;
                ov.x = a0 * silu_f(g0);
                ov.y = a1 * silu_f(g1);
                *(float2*)(Y + ((size_t)b * CC + o) * S + s0 + c) = ov;
            }
        }
    }
}

// ---------------- Attention (SIMT) ----------------
#define ATT_SMEM_FLOATS (128*72 + 2*64*136)
#define ATT_SMEM_BYTES  (ATT_SMEM_FLOATS * 4)

__global__ __launch_bounds__(256)
void attn_kernel(const float* __restrict__ q, const float* __restrict__ kmat,
                 const float* __restrict__ vmat, const float* __restrict__ basis,
                 const float* __restrict__ ss_p, const float* __restrict__ ps_p,
                 float* __restrict__ att)
{
    extern __shared__ float smf[];
    float* Ks  = smf;
    float* Qs  = smf + 128 * 72;
    float* Vt  = Qs;
    float* Wsm = Qs + 64 * 136;

    int fb = blockIdx.x * 128;
    int t  = blockIdx.y;
    int b  = blockIdx.z;
    int tid = threadIdx.x;
    int tx = tid & 15, ty = tid >> 4;

    const float* kb = kmat + (size_t)b * CC * S_LAT + t * KK;
    #pragma unroll
    for (int it = 0; it < 8; it++) {
        int idx = tid + it * 256;
        int c = idx >> 4, kq = idx & 15;
        float4 v = *(const float4*)(kb + (size_t)c * S_LAT + kq * 4);
        *(float4*)&Ks[c * 72 + kq * 4] = v;
    }
    const float* qb = q + (size_t)b * CC * S_SIDE + t * FF + fb;
    #pragma unroll
    for (int it = 0; it < 16; it++) {
        int idx = tid + it * 256;
        int c = idx >> 5, fq = idx & 31;
        float4 v = *(const float4*)(qb + (size_t)c * S_SIDE + fq * 4);
        *(float4*)&Qs[c * 128 + fq * 4] = v;
    }
    __syncthreads();

    u64 sc2[8][2];
    #pragma unroll
    for (int i = 0; i < 8; i++) { sc2[i][0] = 0ull; sc2[i][1] = 0ull; }

    #pragma unroll 4
    for (int c = 0; c < CC; c++) {
        u64 kp0 = *(const u64*)&Ks[c * 72 + tx * 4];
        u64 kp1 = *(const u64*)&Ks[c * 72 + tx * 4 + 2];
        float4 q0 = *(const float4*)&Qs[c * 128 + ty * 8];
        float4 q1 = *(const float4*)&Qs[c * 128 + ty * 8 + 4];
        u64 qd[8] = {dup2(q0.x),dup2(q0.y),dup2(q0.z),dup2(q0.w),
                     dup2(q1.x),dup2(q1.y),dup2(q1.z),dup2(q1.w)};
        #pragma unroll
        for (int i = 0; i < 8; i++) {
            fma2(sc2[i][0], qd[i], kp0);
            fma2(sc2[i][1], qd[i], kp1);
        }
    }
    float sc[8][4];
    #pragma unroll
    for (int i = 0; i < 8; i++) {
        float2 p0 = unpack2(sc2[i][0]);
        float2 p1 = unpack2(sc2[i][1]);
        sc[i][0] = p0.x; sc[i][1] = p0.y; sc[i][2] = p1.x; sc[i][3] = p1.y;
    }
    float ssv = *ss_p, psv = *ps_p;
    #pragma unroll
    for (int i = 0; i < 8; i++)
        #pragma unroll
        for (int j = 0; j < 4; j++)
            sc[i][j] = sc[i][j] * ssv
                     + basis[(tx * 4 + j) * FF + fb + ty * 8 + i] * psv;
    __syncthreads();

    float w[8][4];
    #pragma unroll
    for (int i = 0; i < 8; i++) {
        float m = fmaxf(fmaxf(sc[i][0], sc[i][1]), fmaxf(sc[i][2], sc[i][3]));
        #pragma unroll
        for (int off = 8; off >= 1; off >>= 1)
            m = fmaxf(m, __shfl_xor_sync(0xffffffffu, m, off));
        float e0 = __expf(sc[i][0] - m);
        float e1 = __expf(sc[i][1] - m);
        float e2 = __expf(sc[i][2] - m);
        float e3 = __expf(sc[i][3] - m);
        float s = e0 + e1 + e2 + e3;
        #pragma unroll
        for (int off = 8; off >= 1; off >>= 1)
            s += __shfl_xor_sync(0xffffffffu, s, off);
        float inv = 1.0f / s;
        w[i][0] = e0 * inv; w[i][1] = e1 * inv;
        w[i][2] = e2 * inv; w[i][3] = e3 * inv;
    }
    #pragma unroll
    for (int i = 0; i < 8; i++)
        #pragma unroll
        for (int j = 0; j < 4; j++)
            Wsm[(tx * 4 + j) * 136 + ty * 8 + i] = w[i][j];

    const float* vb = vmat + (size_t)b * CC * S_LAT + t * KK;
    #pragma unroll
    for (int it = 0; it < 8; it++) {
        int idx = tid + it * 256;
        int c = idx >> 4, kq = idx & 15;
        float4 v = *(const float4*)(vb + (size_t)c * S_LAT + kq * 4);
        Vt[(kq * 4 + 0) * 136 + c] = v.x;
        Vt[(kq * 4 + 1) * 136 + c] = v.y;
        Vt[(kq * 4 + 2) * 136 + c] = v.z;
        Vt[(kq * 4 + 3) * 136 + c] = v.w;
    }
    __syncthreads();

    u64 ac2[4][8];
    #pragma unroll
    for (int i = 0; i < 4; i++)
        #pragma unroll
        for (int j = 0; j < 8; j++) ac2[i][j] = 0ull;

    #pragma unroll 4
    for (int k = 0; k < KK; k++) {
        u64 vp[4];
        #pragma unroll
        for (int i = 0; i < 4; i++)
            vp[i] = *(const u64*)&Vt[k * 136 + ty * 8 + 2 * i];
        float4 w0 = *(const float4*)&Wsm[k * 136 + tx * 8];
        float4 w1 = *(const float4*)&Wsm[k * 136 + tx * 8 + 4];
        u64 wd[8] = {dup2(w0.x),dup2(w0.y),dup2(w0.z),dup2(w0.w),
                     dup2(w1.x),dup2(w1.y),dup2(w1.z),dup2(w1.w)};
        #pragma unroll
        for (int i = 0; i < 4; i++)
            #pragma unroll
            for (int j = 0; j < 8; j++)
                fma2(ac2[i][j], vp[i], wd[j]);
    }
    #pragma unroll
    for (int i = 0; i < 4; i++) {
        float r0[8], r1[8];
        #pragma unroll
        for (int j = 0; j < 8; j++) {
            float2 p = unpack2(ac2[i][j]);
            r0[j] = p.x; r1[j] = p.y;
        }
        #pragma unroll
        for (int half = 0; half < 2; half++) {
            int c = ty * 8 + 2 * i + half;
            float* rr = half ? r1 : r0;
            float* orow = att + (((size_t)b * CC + c) * TT + t) * FF + fb + tx * 8;
            *(float4*)(orow + 0) = make_float4(rr[0], rr[1], rr[2], rr[3]);
            *(float4*)(orow + 4) = make_float4(rr[4], rr[5], rr[6], rr[7]);
        }
    }
}

// ---------------- host ----------------
extern "C" void kernel_launch(void* const* d_in, const int* in_sizes, int n_in,
                              void* d_out, int out_size)
{
    const float* latent     = (const float*)d_in[0];
    const float* side       = (const float*)d_in[1];
    const float* basis      = (const float*)d_in[2];
    const float* lp_gamma   = (const float*)d_in[3];
    const float* lp_w       = (const float*)d_in[4];
    const float* lp_b       = (const float*)d_in[5];
    const float* qn_gamma   = (const float*)d_in[6];
    const float* qmlp_in_w  = (const float*)d_in[7];
    const float* qmlp_in_b  = (const float*)d_in[8];
    const float* qmlp_out_w = (const float*)d_in[9];
    const float* qmlp_out_b = (const float*)d_in[10];
    const float* q_w        = (const float*)d_in[11];
    const float* q_b        = (const float*)d_in[12];
    const float* k_w        = (const float*)d_in[13];
    const float* k_b        = (const float*)d_in[14];
    const float* v_w        = (const float*)d_in[15];
    const float* v_b        = (const float*)d_in[16];
    const float* o_w        = (const float*)d_in[17];
    const float* o_b        = (const float*)d_in[18];
    const float* ffn_gamma  = (const float*)d_in[19];
    const float* ffn_in_w   = (const float*)d_in[20];
    const float* ffn_in_b   = (const float*)d_in[21];
    const float* ffn_out_w  = (const float*)d_in[22];
    const float* ffn_out_b  = (const float*)d_in[23];
    const float* score_sc   = (const float*)d_in[24];
    const float* prior_sc   = (const float*)d_in[25];
    const float* qskip_sc   = (const float*)d_in[26];
    float* out = (float*)d_out;

    float *buf1, *buf2, *buf3, *rmsb, *lh, *kmat, *vmat;
    cudaGetSymbolAddress((void**)&buf1, g_buf1);
    cudaGetSymbolAddress((void**)&buf2, g_buf2);
    cudaGetSymbolAddress((void**)&buf3, g_buf3);
    cudaGetSymbolAddress((void**)&rmsb, g_rms);
    cudaGetSymbolAddress((void**)&lh,   g_lh);
    cudaGetSymbolAddress((void**)&kmat, g_k);
    cudaGetSymbolAddress((void**)&vmat, g_v);

    cudaFuncSetAttribute(attn_kernel, cudaFuncAttributeMaxDynamicSharedMemorySize, ATT_SMEM_BYTES);
    cudaFuncSetAttribute(gemm_mm<1,1,0>, cudaFuncAttributeMaxDynamicSharedMemorySize, GT_SMEM);
    cudaFuncSetAttribute(gemm_mm<0,0,0>, cudaFuncAttributeMaxDynamicSharedMemorySize, GT_SMEM);
    cudaFuncSetAttribute(gemm_mm<0,0,1>, cudaFuncAttributeMaxDynamicSharedMemorySize, GT_SMEM);
    cudaFuncSetAttribute(gemm_mm<0,0,2>, cudaFuncAttributeMaxDynamicSharedMemorySize, GT_SMEM);
    cudaFuncSetAttribute(glu_mm<1>,      cudaFuncAttributeMaxDynamicSharedMemorySize, GL_SMEM);

    dim3 blk(256);

    rms_scale_kernel<<<dim3(S_LAT/1024, BB), blk>>>(latent, rmsb, S_LAT);
    gemm_mm<1,1,0><<<dim3(S_LAT/128, BB), blk, GT_SMEM>>>(latent, lp_w, lp_b, lh, nullptr, nullptr, rmsb, lp_gamma, S_LAT);
    gemm_mm<0,0,0><<<dim3(S_LAT/128, BB), blk, GT_SMEM>>>(lh, k_w, k_b, kmat, nullptr, nullptr, nullptr, nullptr, S_LAT);
    gemm_mm<0,0,0><<<dim3(S_LAT/128, BB), blk, GT_SMEM>>>(lh, v_w, v_b, vmat, nullptr, nullptr, nullptr, nullptr, S_LAT);

    rms_scale_kernel<<<dim3(S_SIDE/1024, BB), blk>>>(side, rmsb, S_SIDE);
    glu_mm<1><<<dim3(S_SIDE/128, BB), blk, GL_SMEM>>>(side, qmlp_in_w, qmlp_in_b, buf2, rmsb, qn_gamma, S_SIDE);
    gemm_mm<0,0,0><<<dim3(S_SIDE/128, BB), blk, GT_SMEM>>>(buf2, qmlp_out_w, qmlp_out_b, buf3, nullptr, nullptr, nullptr, nullptr, S_SIDE);
    gemm_mm<0,0,0><<<dim3(S_SIDE/128, BB), blk, GT_SMEM>>>(buf3, q_w, q_b, buf2, nullptr, nullptr, nullptr, nullptr, S_SIDE);

    attn_kernel<<<dim3(FF/128, TT, BB), blk, ATT_SMEM_BYTES>>>(
        buf2, kmat, vmat, basis, score_sc, prior_sc, buf1);

    gemm_mm<0,0,1><<<dim3(S_SIDE/128, BB), blk, GT_SMEM>>>(buf1, o_w, o_b, out, buf3, qskip_sc, nullptr, nullptr, S_SIDE);

    rms_scale_kernel<<<dim3(S_SIDE/1024, BB), blk>>>(out, rmsb, S_SIDE);
    glu_mm<1><<<dim3(S_SIDE/128, BB), blk, GL_SMEM>>>(out, ffn_in_w, ffn_in_b, buf2, rmsb, ffn_gamma, S_SIDE);
    gemm_mm<0,0,2><<<dim3(S_SIDE/128, BB), blk, GT_SMEM>>>(buf2, ffn_out_w, ffn_out_b, out, nullptr, nullptr, nullptr, nullptr, S_SIDE);
}

// round 7
// speedup vs baseline: 1.4268x; 1.0985x over previous
#include <cuda_runtime.h>
#include <cuda_bf16.h>
#include <cstdint>

#define BB 8
#define CC 128
#define TT 128
#define FF 512
#define KK 64
#define S_SIDE (TT*FF)
#define S_LAT  (TT*KK)

typedef unsigned long long u64;
typedef unsigned int u32;
typedef unsigned short u16;

// ---------------- scratch ----------------
__device__ float g_buf1[BB*CC*S_SIDE];            // attention out
__device__ float g_buf2[BB*CC*S_SIDE];            // q (fp32)
__device__ float g_buf3[BB*CC*S_SIDE];            // query_h (fp32, for skip)
__device__ float g_rms [BB*S_SIDE];
__device__ float g_k  [BB*CC*S_LAT];
__device__ float g_v  [BB*CC*S_LAT];

// bf16 hi/lo tile buffers: per (b,tile): 16384 hi + 16384 lo u16
__device__ u16 g_tA[8*512*32768];                 // glu1 out / glu2 out
__device__ u16 g_tB[8*512*32768];                 // qmlp_out out
__device__ u16 g_tL[8*64*32768];                  // latent_h

// pre-converted weights (hi block then lo block per matrix)
#define WLP 0
#define WK  32768
#define WV  65536
#define WQO 98304
#define WQ  131072
#define WO  163840
#define WFO 196608
#define WQI 229376
#define WFI 294912
__device__ u16 g_wbf[360448];

__device__ __forceinline__ float silu_f(float x) { return x / (1.0f + __expf(-x)); }
__device__ __forceinline__ u64 dup2(float v) {
    u64 r; asm("mov.b64 %0, {%1, %2};" : "=l"(r) : "f"(v), "f"(v)); return r;
}
__device__ __forceinline__ void fma2(u64& d, u64 a, u64 b) {
    asm("fma.rn.f32x2 %0, %1, %2, %0;" : "+l"(d) : "l"(a), "l"(b));
}
__device__ __forceinline__ float2 unpack2(u64 v) {
    float2 r; asm("mov.b64 {%0, %1}, %2;" : "=f"(r.x), "=f"(r.y) : "l"(v)); return r;
}
__device__ __forceinline__ u32 smem_u32(const void* p) {
    u32 a;
    asm("{ .reg .u64 t; cvta.to.shared.u64 t, %1; cvt.u32.u64 %0, t; }" : "=r"(a) : "l"(p));
    return a;
}

// ---------------- mma.sync helpers ----------------
__device__ __forceinline__ void ldsm4(u32* r, u32 addr) {
    asm volatile("ldmatrix.sync.aligned.m8n8.x4.shared.b16 {%0,%1,%2,%3}, [%4];"
                 : "=r"(r[0]), "=r"(r[1]), "=r"(r[2]), "=r"(r[3]) : "r"(addr));
}
__device__ __forceinline__ void mma16816(float* d, const u32* a, const u32* b) {
    asm volatile("mma.sync.aligned.m16n8k16.row.col.f32.bf16.bf16.f32 "
                 "{%0,%1,%2,%3}, {%4,%5,%6,%7}, {%8,%9}, {%0,%1,%2,%3};"
                 : "+f"(d[0]), "+f"(d[1]), "+f"(d[2]), "+f"(d[3])
                 : "r"(a[0]), "r"(a[1]), "r"(a[2]), "r"(a[3]), "r"(b[0]), "r"(b[1]));
}
__device__ __forceinline__ void cpa16(u32 saddr, const void* g) {
    asm volatile("cp.async.cg.shared.global [%0], [%1], 16;" :: "r"(saddr), "l"(g));
}
#define CP_COMMIT() asm volatile("cp.async.commit_group;" ::: "memory")
#define CP_WAIT0()  asm volatile("cp.async.wait_group 0;" ::: "memory")

#define TSTR  272
#define TILE_B (128*TSTR)
#define TP 132

// fp32 -> bf16 hi/lo split, store 4 cols to padded smem tiles
__device__ __forceinline__ void cvt_store4(char* smem, u32 hi_base, u32 lo_base,
                                           int row, int col, float4 x) {
    __nv_bfloat16 h0 = __float2bfloat16_rn(x.x); float r0 = x.x - __bfloat162float(h0);
    __nv_bfloat16 h1 = __float2bfloat16_rn(x.y); float r1 = x.y - __bfloat162float(h1);
    __nv_bfloat16 h2 = __float2bfloat16_rn(x.z); float r2 = x.z - __bfloat162float(h2);
    __nv_bfloat16 h3 = __float2bfloat16_rn(x.w); float r3 = x.w - __bfloat162float(h3);
    __nv_bfloat16 l0 = __float2bfloat16_rn(r0);
    __nv_bfloat16 l1 = __float2bfloat16_rn(r1);
    __nv_bfloat16 l2 = __float2bfloat16_rn(r2);
    __nv_bfloat16 l3 = __float2bfloat16_rn(r3);
    u64 hv = (u64)*(u16*)&h0 | ((u64)*(u16*)&h1 << 16) | ((u64)*(u16*)&h2 << 32) | ((u64)*(u16*)&h3 << 48);
    u64 lv = (u64)*(u16*)&l0 | ((u64)*(u16*)&l1 << 16) | ((u64)*(u16*)&l2 << 32) | ((u64)*(u16*)&l3 << 48);
    u32 o = (u32)(row * TSTR + col * 2);
    *(u64*)(smem + hi_base + o) = hv;
    *(u64*)(smem + lo_base + o) = lv;
}

__device__ __forceinline__ u32 pack_hl(float v) {
    __nv_bfloat16 h = __float2bfloat16_rn(v);
    float l = v - __bfloat162float(h);
    __nv_bfloat16 lo = __float2bfloat16_rn(l);
    return (u32)*(u16*)&h | ((u32)*(u16*)&lo << 16);
}

// stage one contiguous 128x128 u16 tile into TSTR-padded smem via cp.async
__device__ __forceinline__ void stage_tile(u32 sbase, const u16* g, int tid) {
    #pragma unroll
    for (int it = 0; it < 8; it++) {
        int idx = tid + it * 256;
        int r = idx >> 4, ch = idx & 15;
        cpa16(sbase + r * TSTR + ch * 16, g + r * 128 + ch * 8);
    }
}

// ---------------- weight pre-convert (gamma folded) ----------------
__global__ __launch_bounds__(256)
void convert_w(const float* __restrict__ W, u16* __restrict__ dst,
               const float* __restrict__ gamma, int n)
{
    int idx = blockIdx.x * 256 + threadIdx.x;
    if (idx >= n) return;
    float v = W[idx];
    if (gamma) v *= gamma[idx & 127];
    __nv_bfloat16 h = __float2bfloat16_rn(v);
    float l = v - __bfloat162float(h);
    __nv_bfloat16 lo = __float2bfloat16_rn(l);
    dst[idx] = *(u16*)&h;
    dst[n + idx] = *(u16*)&lo;
}

// ---------------- inv-RMS ----------------
__global__ __launch_bounds__(256)
void rms_scale_kernel(const float* __restrict__ X, float* __restrict__ R, int S)
{
    int b = blockIdx.y;
    int s = blockIdx.x * 1024 + threadIdx.x * 4;
    const float* xb = X + (size_t)b * CC * S + s;
    float4 acc = make_float4(0.f, 0.f, 0.f, 0.f);
    #pragma unroll 4
    for (int c = 0; c < CC; c++) {
        float4 v = *(const float4*)(xb + (size_t)c * S);
        acc.x += v.x * v.x; acc.y += v.y * v.y;
        acc.z += v.z * v.z; acc.w += v.w * v.w;
    }
    const float inv = 1.0f / CC;
    float4 r;
    r.x = rsqrtf(acc.x * inv + 1e-6f);
    r.y = rsqrtf(acc.y * inv + 1e-6f);
    r.z = rsqrtf(acc.z * inv + 1e-6f);
    r.w = rsqrtf(acc.w * inv + 1e-6f);
    *(float4*)(R + (size_t)b * S + s) = r;
}

// ================= GEMM smem layout =================
#define GT_AHI 0
#define GT_ALO (GT_AHI + TILE_B)
#define GT_BHI (GT_ALO + TILE_B)
#define GT_BLO (GT_BHI + TILE_B)
#define GT_SMEM (GT_BLO + TILE_B)

// ---- shared epilogue macro body implemented inline in each kernel ----

// ================= GEMM, bf16-tile input =================
// OUTFMT: 0 fp32 only, 1 tile only, 2 both. EPI: 0 none, 1 +scl*extra, 2 +=Y
template<int EPI, int OUTFMT>
__global__ __launch_bounds__(256)
void gemm_bfin(const u16* __restrict__ wsc, const float* __restrict__ bias,
               const u16* __restrict__ tin, u16* __restrict__ tout,
               float* __restrict__ Y, const float* __restrict__ extra,
               const float* __restrict__ sc_p, int S)
{
    extern __shared__ char sm[];
    u32 sb = smem_u32(sm);
    int tid = threadIdx.x;
    int wid = tid >> 5, lane = tid & 31;
    int b  = blockIdx.y;
    int s0 = blockIdx.x * 128;
    size_t tb = ((size_t)(b * gridDim.x + blockIdx.x)) * 32768;

    stage_tile(sb + GT_AHI, wsc, tid);
    stage_tile(sb + GT_ALO, wsc + 16384, tid);
    stage_tile(sb + GT_BHI, tin + tb, tid);
    stage_tile(sb + GT_BLO, tin + tb + 16384, tid);
    CP_COMMIT();
    CP_WAIT0();
    __syncthreads();

    int m_blk = (wid & 3) * 32;
    int n_blk = (wid >> 2) * 64;
    float acc[2][8][4];
    #pragma unroll
    for (int i = 0; i < 2; i++)
        #pragma unroll
        for (int j = 0; j < 8; j++)
            #pragma unroll
            for (int q = 0; q < 4; q++) acc[i][j][q] = 0.f;

    u32 a_row = (u32)(m_blk + (lane & 15));
    u32 a_koff = (u32)((lane >> 4) << 3);
    u32 b_row = (u32)((lane & 7) + ((lane >> 4) << 3));
    u32 b_koff = (u32)(((lane >> 3) & 1) << 3);

    const u32 abase[3] = {sb + GT_AHI, sb + GT_AHI, sb + GT_ALO};
    const u32 bbase[3] = {sb + GT_BHI, sb + GT_BLO, sb + GT_BHI};

    #pragma unroll
    for (int p = 0; p < 3; p++) {
        u32 ab = abase[p], bbs = bbase[p];
        #pragma unroll
        for (int ks = 0; ks < 8; ks++) {
            int k0 = ks * 16;
            u32 af[2][4], bf[4][4];
            #pragma unroll
            for (int i = 0; i < 2; i++)
                ldsm4(af[i], ab + (a_row + i * 16) * TSTR + (k0 + a_koff) * 2);
            #pragma unroll
            for (int j = 0; j < 4; j++)
                ldsm4(bf[j], bbs + (n_blk + j * 16 + b_row) * TSTR + (k0 + b_koff) * 2);
            #pragma unroll
            for (int i = 0; i < 2; i++)
                #pragma unroll
                for (int j = 0; j < 8; j++)
                    mma16816(acc[i][j], af[i], &bf[j >> 1][(j & 1) * 2]);
        }
    }

    float scl = (EPI == 1) ? *sc_p : 0.f;
    u32* trans = (u32*)(sm + GT_BHI);
    if (OUTFMT >= 1) __syncthreads();
    #pragma unroll
    for (int i = 0; i < 2; i++) {
        #pragma unroll
        for (int j = 0; j < 8; j++) {
            int c = n_blk + j * 8 + (lane & 3) * 2;
            #pragma unroll
            for (int h = 0; h < 2; h++) {
                int o = m_blk + i * 16 + (lane >> 2) + h * 8;
                float bv = bias[o];
                float v0 = acc[i][j][h * 2 + 0] + bv;
                float v1 = acc[i][j][h * 2 + 1] + bv;
                if (OUTFMT != 1) {
                    float* yp = Y + ((size_t)b * CC + o) * S + s0 + c;
                    float w0 = v0, w1 = v1;
                    if (EPI == 1) {
                        const float* ep = extra + ((size_t)b * CC + o) * S + s0 + c;
                        w0 += scl * ep[0]; w1 += scl * ep[1];
                    }
                    if (EPI == 2) { w0 += yp[0]; w1 += yp[1]; }
                    float2 ov; ov.x = w0; ov.y = w1;
                    *(float2*)yp = ov;
                }
                if (OUTFMT >= 1) {
                    trans[c * TP + o] = pack_hl(v0);
                    trans[(c + 1) * TP + o] = pack_hl(v1);
                }
            }
        }
    }
    if (OUTFMT >= 1) {
        __syncthreads();
        u16* thi = tout + tb;
        u16* tlo = thi + 16384;
        #pragma unroll
        for (int it = 0; it < 16; it++) {
            int idx = tid + it * 256;
            int s = idx >> 5, c0 = (idx & 31) * 4;
            uint4 w = *(const uint4*)(trans + s * TP + c0);
            u64 hv = (u64)(w.x & 0xffff) | ((u64)(w.y & 0xffff) << 16)
                   | ((u64)(w.z & 0xffff) << 32) | ((u64)(w.w & 0xffff) << 48);
            u64 lv = (u64)(w.x >> 16) | ((u64)(w.y >> 16) << 16)
                   | ((u64)(w.z >> 16) << 32) | ((u64)(w.w >> 16) << 48);
            *(u64*)(thi + s * 128 + c0) = hv;
            *(u64*)(tlo + s * 128 + c0) = lv;
        }
    }
}

// ================= GEMM, fp32 input =================
template<int NORM, int ACT, int EPI, int OUTFMT>
__global__ __launch_bounds__(256)
void gemm_f32in(const float* __restrict__ X, const u16* __restrict__ wsc,
                const float* __restrict__ bias, float* __restrict__ Y,
                const float* __restrict__ extra, const float* __restrict__ sc_p,
                const float* __restrict__ rms, u16* __restrict__ tout, int S)
{
    extern __shared__ char sm[];
    u32 sb = smem_u32(sm);
    int tid = threadIdx.x;
    int wid = tid >> 5, lane = tid & 31;
    int b  = blockIdx.y;
    int s0 = blockIdx.x * 128;
    size_t tb = ((size_t)(b * gridDim.x + blockIdx.x)) * 32768;
    const float* Xb = X + (size_t)b * CC * S;

    stage_tile(sb + GT_AHI, wsc, tid);
    stage_tile(sb + GT_ALO, wsc + 16384, tid);
    {
        float rv[4];
        #pragma unroll
        for (int j = 0; j < 4; j++)
            rv[j] = NORM ? rms[(size_t)b * S + s0 + lane + j * 32] : 1.0f;
        #pragma unroll
        for (int i = 0; i < 16; i++) {
            int s = lane + (i & 3) * 32;
            int c0 = ((wid << 2) + (i >> 2)) * 4;
            float4 x4;
            x4.x = Xb[(size_t)(c0 + 0) * S + s0 + s];
            x4.y = Xb[(size_t)(c0 + 1) * S + s0 + s];
            x4.z = Xb[(size_t)(c0 + 2) * S + s0 + s];
            x4.w = Xb[(size_t)(c0 + 3) * S + s0 + s];
            if (NORM) {
                float r = rv[i & 3];
                x4.x *= r; x4.y *= r; x4.z *= r; x4.w *= r;
            }
            cvt_store4(sm, GT_BHI, GT_BLO, s, c0, x4);
        }
    }
    CP_COMMIT();
    CP_WAIT0();
    __syncthreads();

    int m_blk = (wid & 3) * 32;
    int n_blk = (wid >> 2) * 64;
    float acc[2][8][4];
    #pragma unroll
    for (int i = 0; i < 2; i++)
        #pragma unroll
        for (int j = 0; j < 8; j++)
            #pragma unroll
            for (int q = 0; q < 4; q++) acc[i][j][q] = 0.f;

    u32 a_row = (u32)(m_blk + (lane & 15));
    u32 a_koff = (u32)((lane >> 4) << 3);
    u32 b_row = (u32)((lane & 7) + ((lane >> 4) << 3));
    u32 b_koff = (u32)(((lane >> 3) & 1) << 3);

    const u32 abase[3] = {sb + GT_AHI, sb + GT_AHI, sb + GT_ALO};
    const u32 bbase[3] = {sb + GT_BHI, sb + GT_BLO, sb + GT_BHI};

    #pragma unroll
    for (int p = 0; p < 3; p++) {
        u32 ab = abase[p], bbs = bbase[p];
        #pragma unroll
        for (int ks = 0; ks < 8; ks++) {
            int k0 = ks * 16;
            u32 af[2][4], bf[4][4];
            #pragma unroll
            for (int i = 0; i < 2; i++)
                ldsm4(af[i], ab + (a_row + i * 16) * TSTR + (k0 + a_koff) * 2);
            #pragma unroll
            for (int j = 0; j < 4; j++)
                ldsm4(bf[j], bbs + (n_blk + j * 16 + b_row) * TSTR + (k0 + b_koff) * 2);
            #pragma unroll
            for (int i = 0; i < 2; i++)
                #pragma unroll
                for (int j = 0; j < 8; j++)
                    mma16816(acc[i][j], af[i], &bf[j >> 1][(j & 1) * 2]);
        }
    }

    float scl = (EPI == 1) ? *sc_p : 0.f;
    u32* trans = (u32*)(sm + GT_BHI);
    if (OUTFMT >= 1) __syncthreads();
    #pragma unroll
    for (int i = 0; i < 2; i++) {
        #pragma unroll
        for (int j = 0; j < 8; j++) {
            int c = n_blk + j * 8 + (lane & 3) * 2;
            #pragma unroll
            for (int h = 0; h < 2; h++) {
                int o = m_blk + i * 16 + (lane >> 2) + h * 8;
                float bv = bias[o];
                float v0 = acc[i][j][h * 2 + 0] + bv;
                float v1 = acc[i][j][h * 2 + 1] + bv;
                if (ACT == 1) { v0 = silu_f(v0); v1 = silu_f(v1); }
                if (OUTFMT != 1) {
                    float* yp = Y + ((size_t)b * CC + o) * S + s0 + c;
                    float w0 = v0, w1 = v1;
                    if (EPI == 1) {
                        const float* ep = extra + ((size_t)b * CC + o) * S + s0 + c;
                        w0 += scl * ep[0]; w1 += scl * ep[1];
                    }
                    if (EPI == 2) { w0 += yp[0]; w1 += yp[1]; }
                    float2 ov; ov.x = w0; ov.y = w1;
                    *(float2*)yp = ov;
                }
                if (OUTFMT >= 1) {
                    trans[c * TP + o] = pack_hl(v0);
                    trans[(c + 1) * TP + o] = pack_hl(v1);
                }
            }
        }
    }
    if (OUTFMT >= 1) {
        __syncthreads();
        u16* thi = tout + tb;
        u16* tlo = thi + 16384;
        #pragma unroll
        for (int it = 0; it < 16; it++) {
            int idx = tid + it * 256;
            int s = idx >> 5, c0 = (idx & 31) * 4;
            uint4 w = *(const uint4*)(trans + s * TP + c0);
            u64 hv = (u64)(w.x & 0xffff) | ((u64)(w.y & 0xffff) << 16)
                   | ((u64)(w.z & 0xffff) << 32) | ((u64)(w.w & 0xffff) << 48);
            u64 lv = (u64)(w.x >> 16) | ((u64)(w.y >> 16) << 16)
                   | ((u64)(w.z >> 16) << 32) | ((u64)(w.w >> 16) << 48);
            *(u64*)(thi + s * 128 + c0) = hv;
            *(u64*)(tlo + s * 128 + c0) = lv;
        }
    }
}

// ================= GLU (fp32 input w/ rms, bf16 tile output) =================
#define GL_AAHI 0
#define GL_AALO (GL_AAHI + TILE_B)
#define GL_AGHI (GL_AALO + TILE_B)
#define GL_AGLO (GL_AGHI + TILE_B)
#define GL_BHI  (GL_AGLO + TILE_B)
#define GL_BLO  (GL_BHI  + TILE_B)
#define GL_SMEM (GL_BLO  + TILE_B)

__global__ __launch_bounds__(256)
void glu_mm(const float* __restrict__ X, const u16* __restrict__ wsc,
            const float* __restrict__ bias, u16* __restrict__ tout,
            const float* __restrict__ rms, int S)
{
    extern __shared__ char sm[];
    u32 sb = smem_u32(sm);
    int tid = threadIdx.x;
    int wid = tid >> 5, lane = tid & 31;
    int b  = blockIdx.y;
    int s0 = blockIdx.x * 128;
    size_t tb = ((size_t)(b * gridDim.x + blockIdx.x)) * 32768;
    const float* Xb = X + (size_t)b * CC * S;

    // weights: hi[256x128] at wsc, lo at wsc+32768
    stage_tile(sb + GL_AAHI, wsc, tid);
    stage_tile(sb + GL_AGHI, wsc + 16384, tid);
    stage_tile(sb + GL_AALO, wsc + 32768, tid);
    stage_tile(sb + GL_AGLO, wsc + 49152, tid);
    {
        float rv[4];
        #pragma unroll
        for (int j = 0; j < 4; j++)
            rv[j] = rms[(size_t)b * S + s0 + lane + j * 32];
        #pragma unroll
        for (int i = 0; i < 16; i++) {
            int s = lane + (i & 3) * 32;
            int c0 = ((wid << 2) + (i >> 2)) * 4;
            float4 x4;
            x4.x = Xb[(size_t)(c0 + 0) * S + s0 + s];
            x4.y = Xb[(size_t)(c0 + 1) * S + s0 + s];
            x4.z = Xb[(size_t)(c0 + 2) * S + s0 + s];
            x4.w = Xb[(size_t)(c0 + 3) * S + s0 + s];
            float r = rv[i & 3];
            x4.x *= r; x4.y *= r; x4.z *= r; x4.w *= r;
            cvt_store4(sm, GL_BHI, GL_BLO, s, c0, x4);
        }
    }
    CP_COMMIT();
    CP_WAIT0();
    __syncthreads();

    int m_blk = (wid & 3) * 32;
    int n_blk = (wid >> 2) * 64;
    float acca[2][8][4], accg[2][8][4];
    #pragma unroll
    for (int i = 0; i < 2; i++)
        #pragma unroll
        for (int j = 0; j < 8; j++)
            #pragma unroll
            for (int q = 0; q < 4; q++) { acca[i][j][q] = 0.f; accg[i][j][q] = 0.f; }

    u32 a_row = (u32)(m_blk + (lane & 15));
    u32 a_koff = (u32)((lane >> 4) << 3);
    u32 b_row = (u32)((lane & 7) + ((lane >> 4) << 3));
    u32 b_koff = (u32)(((lane >> 3) & 1) << 3);

    const u32 aab[3] = {sb + GL_AAHI, sb + GL_AAHI, sb + GL_AALO};
    const u32 agb[3] = {sb + GL_AGHI, sb + GL_AGHI, sb + GL_AGLO};
    const u32 bbb[3] = {sb + GL_BHI,  sb + GL_BLO,  sb + GL_BHI };

    #pragma unroll
    for (int p = 0; p < 3; p++) {
        u32 aa = aab[p], ag = agb[p], bbs = bbb[p];
        #pragma unroll
        for (int ks = 0; ks < 8; ks++) {
            int k0 = ks * 16;
            u32 afa[2][4], afg[2][4], bf[4][4];
            #pragma unroll
            for (int i = 0; i < 2; i++) {
                ldsm4(afa[i], aa + (a_row + i * 16) * TSTR + (k0 + a_koff) * 2);
                ldsm4(afg[i], ag + (a_row + i * 16) * TSTR + (k0 + a_koff) * 2);
            }
            #pragma unroll
            for (int j = 0; j < 4; j++)
                ldsm4(bf[j], bbs + (n_blk + j * 16 + b_row) * TSTR + (k0 + b_koff) * 2);
            #pragma unroll
            for (int i = 0; i < 2; i++)
                #pragma unroll
                for (int j = 0; j < 8; j++) {
                    mma16816(acca[i][j], afa[i], &bf[j >> 1][(j & 1) * 2]);
                    mma16816(accg[i][j], afg[i], &bf[j >> 1][(j & 1) * 2]);
                }
        }
    }

    u32* trans = (u32*)(sm + GL_BHI);
    __syncthreads();
    #pragma unroll
    for (int i = 0; i < 2; i++) {
        #pragma unroll
        for (int j = 0; j < 8; j++) {
            int c = n_blk + j * 8 + (lane & 3) * 2;
            #pragma unroll
            for (int h = 0; h < 2; h++) {
                int o = m_blk + i * 16 + (lane >> 2) + h * 8;
                float ba = bias[o], bg = bias[CC + o];
                float v0 = (acca[i][j][h * 2 + 0] + ba) * silu_f(accg[i][j][h * 2 + 0] + bg);
                float v1 = (acca[i][j][h * 2 + 1] + ba) * silu_f(accg[i][j][h * 2 + 1] + bg);
                trans[c * TP + o] = pack_hl(v0);
                trans[(c + 1) * TP + o] = pack_hl(v1);
            }
        }
    }
    __syncthreads();
    {
        u16* thi = tout + tb;
        u16* tlo = thi + 16384;
        #pragma unroll
        for (int it = 0; it < 16; it++) {
            int idx = tid + it * 256;
            int s = idx >> 5, c0 = (idx & 31) * 4;
            uint4 w = *(const uint4*)(trans + s * TP + c0);
            u64 hv = (u64)(w.x & 0xffff) | ((u64)(w.y & 0xffff) << 16)
                   | ((u64)(w.z & 0xffff) << 32) | ((u64)(w.w & 0xffff) << 48);
            u64 lv = (u64)(w.x >> 16) | ((u64)(w.y >> 16) << 16)
                   | ((u64)(w.z >> 16) << 32) | ((u64)(w.w >> 16) << 48);
            *(u64*)(thi + s * 128 + c0) = hv;
            *(u64*)(tlo + s * 128 + c0) = lv;
        }
    }
}

// ---------------- Attention (SIMT) ----------------
#define ATT_SMEM_FLOATS (128*72 + 2*64*136)
#define ATT_SMEM_BYTES  (ATT_SMEM_FLOATS * 4)

__global__ __launch_bounds__(256)
void attn_kernel(const float* __restrict__ q, const float* __restrict__ kmat,
                 const float* __restrict__ vmat, const float* __restrict__ basis,
                 const float* __restrict__ ss_p, const float* __restrict__ ps_p,
                 float* __restrict__ att)
{
    extern __shared__ float smf[];
    float* Ks  = smf;
    float* Qs  = smf + 128 * 72;
    float* Vt  = Qs;
    float* Wsm = Qs + 64 * 136;

    int fb = blockIdx.x * 128;
    int t  = blockIdx.y;
    int b  = blockIdx.z;
    int tid = threadIdx.x;
    int tx = tid & 15, ty = tid >> 4;

    const float* kb = kmat + (size_t)b * CC * S_LAT + t * KK;
    #pragma unroll
    for (int it = 0; it < 8; it++) {
        int idx = tid + it * 256;
        int c = idx >> 4, kq = idx & 15;
        float4 v = *(const float4*)(kb + (size_t)c * S_LAT + kq * 4);
        *(float4*)&Ks[c * 72 + kq * 4] = v;
    }
    const float* qb = q + (size_t)b * CC * S_SIDE + t * FF + fb;
    #pragma unroll
    for (int it = 0; it < 16; it++) {
        int idx = tid + it * 256;
        int c = idx >> 5, fq = idx & 31;
        float4 v = *(const float4*)(qb + (size_t)c * S_SIDE + fq * 4);
        *(float4*)&Qs[c * 128 + fq * 4] = v;
    }
    __syncthreads();

    u64 sc2[8][2];
    #pragma unroll
    for (int i = 0; i < 8; i++) { sc2[i][0] = 0ull; sc2[i][1] = 0ull; }

    #pragma unroll 4
    for (int c = 0; c < CC; c++) {
        u64 kp0 = *(const u64*)&Ks[c * 72 + tx * 4];
        u64 kp1 = *(const u64*)&Ks[c * 72 + tx * 4 + 2];
        float4 q0 = *(const float4*)&Qs[c * 128 + ty * 8];
        float4 q1 = *(const float4*)&Qs[c * 128 + ty * 8 + 4];
        u64 qd[8] = {dup2(q0.x),dup2(q0.y),dup2(q0.z),dup2(q0.w),
                     dup2(q1.x),dup2(q1.y),dup2(q1.z),dup2(q1.w)};
        #pragma unroll
        for (int i = 0; i < 8; i++) {
            fma2(sc2[i][0], qd[i], kp0);
            fma2(sc2[i][1], qd[i], kp1);
        }
    }
    float sc[8][4];
    #pragma unroll
    for (int i = 0; i < 8; i++) {
        float2 p0 = unpack2(sc2[i][0]);
        float2 p1 = unpack2(sc2[i][1]);
        sc[i][0] = p0.x; sc[i][1] = p0.y; sc[i][2] = p1.x; sc[i][3] = p1.y;
    }
    float ssv = *ss_p, psv = *ps_p;
    #pragma unroll
    for (int i = 0; i < 8; i++)
        #pragma unroll
        for (int j = 0; j < 4; j++)
            sc[i][j] = sc[i][j] * ssv
                     + basis[(tx * 4 + j) * FF + fb + ty * 8 + i] * psv;
    __syncthreads();

    float w[8][4];
    #pragma unroll
    for (int i = 0; i < 8; i++) {
        float m = fmaxf(fmaxf(sc[i][0], sc[i][1]), fmaxf(sc[i][2], sc[i][3]));
        #pragma unroll
        for (int off = 8; off >= 1; off >>= 1)
            m = fmaxf(m, __shfl_xor_sync(0xffffffffu, m, off));
        float e0 = __expf(sc[i][0] - m);
        float e1 = __expf(sc[i][1] - m);
        float e2 = __expf(sc[i][2] - m);
        float e3 = __expf(sc[i][3] - m);
        float s = e0 + e1 + e2 + e3;
        #pragma unroll
        for (int off = 8; off >= 1; off >>= 1)
            s += __shfl_xor_sync(0xffffffffu, s, off);
        float inv = 1.0f / s;
        w[i][0] = e0 * inv; w[i][1] = e1 * inv;
        w[i][2] = e2 * inv; w[i][3] = e3 * inv;
    }
    #pragma unroll
    for (int i = 0; i < 8; i++)
        #pragma unroll
        for (int j = 0; j < 4; j++)
            Wsm[(tx * 4 + j) * 136 + ty * 8 + i] = w[i][j];

    const float* vb = vmat + (size_t)b * CC * S_LAT + t * KK;
    #pragma unroll
    for (int it = 0; it < 8; it++) {
        int idx = tid + it * 256;
        int c = idx >> 4, kq = idx & 15;
        float4 v = *(const float4*)(vb + (size_t)c * S_LAT + kq * 4);
        Vt[(kq * 4 + 0) * 136 + c] = v.x;
        Vt[(kq * 4 + 1) * 136 + c] = v.y;
        Vt[(kq * 4 + 2) * 136 + c] = v.z;
        Vt[(kq * 4 + 3) * 136 + c] = v.w;
    }
    __syncthreads();

    u64 ac2[4][8];
    #pragma unroll
    for (int i = 0; i < 4; i++)
        #pragma unroll
        for (int j = 0; j < 8; j++) ac2[i][j] = 0ull;

    #pragma unroll 4
    for (int k = 0; k < KK; k++) {
        u64 vp[4];
        #pragma unroll
        for (int i = 0; i < 4; i++)
            vp[i] = *(const u64*)&Vt[k * 136 + ty * 8 + 2 * i];
        float4 w0 = *(const float4*)&Wsm[k * 136 + tx * 8];
        float4 w1 = *(const float4*)&Wsm[k * 136 + tx * 8 + 4];
        u64 wd[8] = {dup2(w0.x),dup2(w0.y),dup2(w0.z),dup2(w0.w),
                     dup2(w1.x),dup2(w1.y),dup2(w1.z),dup2(w1.w)};
        #pragma unroll
        for (int i = 0; i < 4; i++)
            #pragma unroll
            for (int j = 0; j < 8; j++)
                fma2(ac2[i][j], vp[i], wd[j]);
    }
    #pragma unroll
    for (int i = 0; i < 4; i++) {
        float r0[8], r1[8];
        #pragma unroll
        for (int j = 0; j < 8; j++) {
            float2 p = unpack2(ac2[i][j]);
            r0[j] = p.x; r1[j] = p.y;
        }
        #pragma unroll
        for (int half = 0; half < 2; half++) {
            int c = ty * 8 + 2 * i + half;
            float* rr = half ? r1 : r0;
            float* orow = att + (((size_t)b * CC + c) * TT + t) * FF + fb + tx * 8;
            *(float4*)(orow + 0) = make_float4(rr[0], rr[1], rr[2], rr[3]);
            *(float4*)(orow + 4) = make_float4(rr[4], rr[5], rr[6], rr[7]);
        }
    }
}

// ---------------- host ----------------
extern "C" void kernel_launch(void* const* d_in, const int* in_sizes, int n_in,
                              void* d_out, int out_size)
{
    const float* latent     = (const float*)d_in[0];
    const float* side       = (const float*)d_in[1];
    const float* basis      = (const float*)d_in[2];
    const float* lp_gamma   = (const float*)d_in[3];
    const float* lp_w       = (const float*)d_in[4];
    const float* lp_b       = (const float*)d_in[5];
    const float* qn_gamma   = (const float*)d_in[6];
    const float* qmlp_in_w  = (const float*)d_in[7];
    const float* qmlp_in_b  = (const float*)d_in[8];
    const float* qmlp_out_w = (const float*)d_in[9];
    const float* qmlp_out_b = (const float*)d_in[10];
    const float* q_w        = (const float*)d_in[11];
    const float* q_b        = (const float*)d_in[12];
    const float* k_w        = (const float*)d_in[13];
    const float* k_b        = (const float*)d_in[14];
    const float* v_w        = (const float*)d_in[15];
    const float* v_b        = (const float*)d_in[16];
    const float* o_w        = (const float*)d_in[17];
    const float* o_b        = (const float*)d_in[18];
    const float* ffn_gamma  = (const float*)d_in[19];
    const float* ffn_in_w   = (const float*)d_in[20];
    const float* ffn_in_b   = (const float*)d_in[21];
    const float* ffn_out_w  = (const float*)d_in[22];
    const float* ffn_out_b  = (const float*)d_in[23];
    const float* score_sc   = (const float*)d_in[24];
    const float* prior_sc   = (const float*)d_in[25];
    const float* qskip_sc   = (const float*)d_in[26];
    float* out = (float*)d_out;

    float *buf1, *buf2, *buf3, *rmsb, *kmat, *vmat;
    u16 *tA, *tB, *tL, *wbf;
    cudaGetSymbolAddress((void**)&buf1, g_buf1);
    cudaGetSymbolAddress((void**)&buf2, g_buf2);
    cudaGetSymbolAddress((void**)&buf3, g_buf3);
    cudaGetSymbolAddress((void**)&rmsb, g_rms);
    cudaGetSymbolAddress((void**)&kmat, g_k);
    cudaGetSymbolAddress((void**)&vmat, g_v);
    cudaGetSymbolAddress((void**)&tA,   g_tA);
    cudaGetSymbolAddress((void**)&tB,   g_tB);
    cudaGetSymbolAddress((void**)&tL,   g_tL);
    cudaGetSymbolAddress((void**)&wbf,  g_wbf);

    cudaFuncSetAttribute(attn_kernel, cudaFuncAttributeMaxDynamicSharedMemorySize, ATT_SMEM_BYTES);
    cudaFuncSetAttribute(gemm_f32in<1,1,0,1>, cudaFuncAttributeMaxDynamicSharedMemorySize, GT_SMEM);
    cudaFuncSetAttribute(gemm_f32in<0,0,1,0>, cudaFuncAttributeMaxDynamicSharedMemorySize, GT_SMEM);
    cudaFuncSetAttribute(gemm_bfin<0,0>, cudaFuncAttributeMaxDynamicSharedMemorySize, GT_SMEM);
    cudaFuncSetAttribute(gemm_bfin<0,2>, cudaFuncAttributeMaxDynamicSharedMemorySize, GT_SMEM);
    cudaFuncSetAttribute(gemm_bfin<2,0>, cudaFuncAttributeMaxDynamicSharedMemorySize, GT_SMEM);
    cudaFuncSetAttribute(glu_mm, cudaFuncAttributeMaxDynamicSharedMemorySize, GL_SMEM);

    dim3 blk(256);

    // ---- pre-convert weights (gamma folded where the reference does rmsnorm) ----
    convert_w<<<64, blk>>>(lp_w,       wbf + WLP, lp_gamma, 16384);
    convert_w<<<64, blk>>>(k_w,        wbf + WK,  nullptr,  16384);
    convert_w<<<64, blk>>>(v_w,        wbf + WV,  nullptr,  16384);
    convert_w<<<64, blk>>>(qmlp_out_w, wbf + WQO, nullptr,  16384);
    convert_w<<<64, blk>>>(q_w,        wbf + WQ,  nullptr,  16384);
    convert_w<<<64, blk>>>(o_w,        wbf + WO,  nullptr,  16384);
    convert_w<<<64, blk>>>(ffn_out_w,  wbf + WFO, nullptr,  16384);
    convert_w<<<128, blk>>>(qmlp_in_w, wbf + WQI, qn_gamma, 32768);
    convert_w<<<128, blk>>>(ffn_in_w,  wbf + WFI, ffn_gamma, 32768);

    // ---- latent path ----
    rms_scale_kernel<<<dim3(S_LAT/1024, BB), blk>>>(latent, rmsb, S_LAT);
    gemm_f32in<1,1,0,1><<<dim3(S_LAT/128, BB), blk, GT_SMEM>>>(
        latent, wbf + WLP, lp_b, nullptr, nullptr, nullptr, rmsb, tL, S_LAT);
    gemm_bfin<0,0><<<dim3(S_LAT/128, BB), blk, GT_SMEM>>>(
        wbf + WK, k_b, tL, nullptr, kmat, nullptr, nullptr, S_LAT);
    gemm_bfin<0,0><<<dim3(S_LAT/128, BB), blk, GT_SMEM>>>(
        wbf + WV, v_b, tL, nullptr, vmat, nullptr, nullptr, S_LAT);

    // ---- side / query path ----
    rms_scale_kernel<<<dim3(S_SIDE/1024, BB), blk>>>(side, rmsb, S_SIDE);
    glu_mm<<<dim3(S_SIDE/128, BB), blk, GL_SMEM>>>(side, wbf + WQI, qmlp_in_b, tA, rmsb, S_SIDE);
    gemm_bfin<0,2><<<dim3(S_SIDE/128, BB), blk, GT_SMEM>>>(
        wbf + WQO, qmlp_out_b, tA, tB, buf3, nullptr, nullptr, S_SIDE);
    gemm_bfin<0,0><<<dim3(S_SIDE/128, BB), blk, GT_SMEM>>>(
        wbf + WQ, q_b, tB, nullptr, buf2, nullptr, nullptr, S_SIDE);

    // ---- attention ----
    attn_kernel<<<dim3(FF/128, TT, BB), blk, ATT_SMEM_BYTES>>>(
        buf2, kmat, vmat, basis, score_sc, prior_sc, buf1);

    // ---- output projection + query skip ----
    gemm_f32in<0,0,1,0><<<dim3(S_SIDE/128, BB), blk, GT_SMEM>>>(
        buf1, wbf + WO, o_b, out, buf3, qskip_sc, nullptr, nullptr, S_SIDE);

    // ---- FFN ----
    rms_scale_kernel<<<dim3(S_SIDE/1024, BB), blk>>>(out, rmsb, S_SIDE);
    glu_mm<<<dim3(S_SIDE/128, BB), blk, GL_SMEM>>>(out, wbf + WFI, ffn_in_b, tA, rmsb, S_SIDE);
    gemm_bfin<2,0><<<dim3(S_SIDE/128, BB), blk, GT_SMEM>>>(
        wbf + WFO, ffn_out_b, tA, nullptr, out, nullptr, nullptr, S_SIDE);
}